// round 1
// baseline (speedup 1.0000x reference)
#include <cuda_runtime.h>

// Problem constants
static constexpr int BATCH = 32;
static constexpr int NH    = 8;
// all big matrices are 512x512 with ld 512

// ---------------------------------------------------------------------------
// Scratch (static __device__ arrays: allocation-free per harness rules)
// ---------------------------------------------------------------------------
__device__ float g_Wc_in [512 * 512];
__device__ float g_Wc_out[512 * 512];
__device__ float g_xp    [(long)BATCH * 512 * 512];
__device__ float g_q     [(long)BATCH * NH * 512 * 64];
__device__ float g_k     [(long)BATCH * NH * 512 * 64];
__device__ float g_v     [(long)BATCH * NH * 512 * 64];
__device__ float g_cc    [(long)BATCH * 512 * 512];
__device__ float g_oi    [(long)BATCH * 512 * 512];

// ---------------------------------------------------------------------------
// Generic batched 512x512x512 SGEMM:  C[b][m][n] = sum_k opA[m,k] * opB[n,k]
//   AT=false: A[m*512+k] (row-major, K contiguous)   AT=true: A[k*512+m]
//   BT=false: B[n*512+k]                             BT=true: B[k*512+n]
//   EPI 0: C=acc   1: C=acc+R   2: C=(1-a)*acc + a*R, a=sigmoid(*alpha_ptr)
// Tile 128x128, BK=8, 256 threads, 8x8 microtile per thread.
// ---------------------------------------------------------------------------
template<bool AT, bool BT, int EPI>
__global__ __launch_bounds__(256) void gemm512(
    const float* __restrict__ A, long sA,
    const float* __restrict__ B, long sB,
    float* __restrict__ C, long sC,
    const float* __restrict__ R, long sR,
    const float* __restrict__ alpha_ptr)
{
    __shared__ float As[8][128];
    __shared__ float Bs[8][128];
    const int bN = blockIdx.x * 128;
    const int bM = blockIdx.y * 128;
    const int bz = blockIdx.z;
    A += (long)bz * sA;
    B += (long)bz * sB;
    C += (long)bz * sC;
    if (EPI != 0) R += (long)bz * sR;

    const int tid  = threadIdx.x;
    const int tx   = tid & 15;
    const int ty   = tid >> 4;
    const int lk   = tid >> 5;          // T layout: k row of tile
    const int lm   = (tid & 31) << 2;   // T layout: 4-float col offset
    const int lrow = tid >> 1;          // N layout: row within tile
    const int lq   = (tid & 1) << 2;    // N layout: 4-float k offset

    float acc[8][8];
    #pragma unroll
    for (int i = 0; i < 8; i++)
        #pragma unroll
        for (int j = 0; j < 8; j++) acc[i][j] = 0.f;

    for (int kt = 0; kt < 64; kt++) {
        const int k0 = kt * 8;
        float4 ar, br;
        if (AT) ar = *(const float4*)(A + (long)(k0 + lk) * 512 + bM + lm);
        else    ar = *(const float4*)(A + (long)(bM + lrow) * 512 + k0 + lq);
        if (BT) br = *(const float4*)(B + (long)(k0 + lk) * 512 + bN + lm);
        else    br = *(const float4*)(B + (long)(bN + lrow) * 512 + k0 + lq);
        __syncthreads();
        if (AT) { *(float4*)&As[lk][lm] = ar; }
        else {
            As[lq + 0][lrow] = ar.x; As[lq + 1][lrow] = ar.y;
            As[lq + 2][lrow] = ar.z; As[lq + 3][lrow] = ar.w;
        }
        if (BT) { *(float4*)&Bs[lk][lm] = br; }
        else {
            Bs[lq + 0][lrow] = br.x; Bs[lq + 1][lrow] = br.y;
            Bs[lq + 2][lrow] = br.z; Bs[lq + 3][lrow] = br.w;
        }
        __syncthreads();
        #pragma unroll
        for (int k = 0; k < 8; k++) {
            float4 a0 = *(const float4*)&As[k][ty * 4];
            float4 a1 = *(const float4*)&As[k][ty * 4 + 64];
            float4 b0 = *(const float4*)&Bs[k][tx * 4];
            float4 b1 = *(const float4*)&Bs[k][tx * 4 + 64];
            float av[8] = {a0.x, a0.y, a0.z, a0.w, a1.x, a1.y, a1.z, a1.w};
            float bv[8] = {b0.x, b0.y, b0.z, b0.w, b1.x, b1.y, b1.z, b1.w};
            #pragma unroll
            for (int i = 0; i < 8; i++)
                #pragma unroll
                for (int j = 0; j < 8; j++)
                    acc[i][j] = fmaf(av[i], bv[j], acc[i][j]);
        }
    }

    float ab = 0.f;
    if (EPI == 2) ab = 1.f / (1.f + expf(-alpha_ptr[0]));
    #pragma unroll
    for (int i = 0; i < 8; i++) {
        const int m = bM + ((i >> 2) << 6) + ty * 4 + (i & 3);
        #pragma unroll
        for (int cg = 0; cg < 2; cg++) {
            const int n = bN + cg * 64 + tx * 4;
            float4 v;
            v.x = acc[i][cg * 4 + 0]; v.y = acc[i][cg * 4 + 1];
            v.z = acc[i][cg * 4 + 2]; v.w = acc[i][cg * 4 + 3];
            if (EPI == 1) {
                float4 r = *(const float4*)(R + (long)m * 512 + n);
                v.x += r.x; v.y += r.y; v.z += r.z; v.w += r.w;
            } else if (EPI == 2) {
                float4 r = *(const float4*)(R + (long)m * 512 + n);
                v.x = (1.f - ab) * v.x + ab * r.x;
                v.y = (1.f - ab) * v.y + ab * r.y;
                v.z = (1.f - ab) * v.z + ab * r.z;
                v.w = (1.f - ab) * v.w + ab * r.w;
            }
            *(float4*)(C + (long)m * 512 + n) = v;
        }
    }
}

// ---------------------------------------------------------------------------
// Per-head projection: O[b,h,n,e] = sum_d X[b, n, h*64+d] * W[h, e, d]
// grid: (8 row-tiles, 24 = which*8+h, 32 batch), 256 threads.
// Output layout: [b*NH+h][512][64]
// ---------------------------------------------------------------------------
__global__ __launch_bounds__(256) void qkv_kernel(
    const float* __restrict__ X,
    const float* __restrict__ Wq, const float* __restrict__ Wk,
    const float* __restrict__ Wv,
    float* __restrict__ Q, float* __restrict__ K, float* __restrict__ V)
{
    __shared__ float Xs[64][64];
    __shared__ float Ws[64][65];
    const int r0    = blockIdx.x * 64;
    const int which = blockIdx.y >> 3;
    const int h     = blockIdx.y & 7;
    const int b     = blockIdx.z;
    const float* W  = (which == 0) ? Wq : (which == 1) ? Wk : Wv;
    float* O        = (which == 0) ? Q  : (which == 1) ? K  : V;
    const int tid = threadIdx.x;
    const int tx = tid & 15, ty = tid >> 4;
    const float* Xb = X + (long)b * 512 * 512;

    for (int i = tid; i < 4096; i += 256) {
        const int r = i >> 6, c = i & 63;
        Xs[r][c] = Xb[(long)(r0 + r) * 512 + h * 64 + c];
        Ws[r][c] = W[h * 4096 + i];   // [e][d] row-major
    }
    __syncthreads();

    float acc[4][4];
    #pragma unroll
    for (int i = 0; i < 4; i++)
        #pragma unroll
        for (int j = 0; j < 4; j++) acc[i][j] = 0.f;

    #pragma unroll 8
    for (int k = 0; k < 64; k++) {
        float xv[4], wv[4];
        #pragma unroll
        for (int i = 0; i < 4; i++) xv[i] = Xs[ty * 4 + i][k];
        #pragma unroll
        for (int j = 0; j < 4; j++) wv[j] = Ws[tx * 4 + j][k];
        #pragma unroll
        for (int i = 0; i < 4; i++)
            #pragma unroll
            for (int j = 0; j < 4; j++)
                acc[i][j] = fmaf(xv[i], wv[j], acc[i][j]);
    }

    float* Ob = O + (long)(b * NH + h) * 512 * 64;
    #pragma unroll
    for (int i = 0; i < 4; i++) {
        float4 v;
        v.x = acc[i][0]; v.y = acc[i][1]; v.z = acc[i][2]; v.w = acc[i][3];
        *(float4*)(Ob + (long)(r0 + ty * 4 + i) * 64 + tx * 4) = v;
    }
}

// ---------------------------------------------------------------------------
// Fused flash-style attention per (b, h, 64-row q tile).
// Q/K/V layout [b*NH+h][512][64]. Output written head-concatenated:
// O[b][n][h*64+e]. Online softmax (running max / sum), P staged via smem.
// Q is pre-scaled by 1/sqrt(64); mask (optional) added post-scale (matches ref).
// ---------------------------------------------------------------------------
static constexpr int ATTN_SMEM = (64 * 64 + 64 * 65 + 64 * 64 + 64 * 65) * 4;

__global__ __launch_bounds__(256) void attn_kernel(
    const float* __restrict__ Q, const float* __restrict__ K,
    const float* __restrict__ V, const float* __restrict__ mask,
    float* __restrict__ O)
{
    extern __shared__ float sm[];
    float* Qs = sm;                // [64][64]
    float* Ks = Qs + 64 * 64;      // [64][65] (padded)
    float* Vs = Ks + 64 * 65;      // [64][64]
    float* Ps = Vs + 64 * 64;      // [64][65] (padded)

    const int q0 = blockIdx.x * 64;
    const int h  = blockIdx.y;
    const int b  = blockIdx.z;
    const long base = (long)(b * NH + h) * 512 * 64;
    const float* Qb = Q + base;
    const float* Kb = K + base;
    const float* Vb = V + base;
    const int tid = threadIdx.x;
    const int tx = tid & 15, ty = tid >> 4;

    for (int i = tid; i < 4096; i += 256) {
        const int r = i >> 6, c = i & 63;
        Qs[r * 64 + c] = Qb[(long)(q0 + r) * 64 + c] * 0.125f; // 1/sqrt(64)
    }

    float mrow[4], lrow[4], o[4][4];
    #pragma unroll
    for (int i = 0; i < 4; i++) {
        mrow[i] = -1e30f; lrow[i] = 0.f;
        #pragma unroll
        for (int j = 0; j < 4; j++) o[i][j] = 0.f;
    }

    for (int kt = 0; kt < 8; kt++) {
        __syncthreads();   // protect Ks/Vs/Ps from previous iteration's readers
        for (int i = tid; i < 4096; i += 256) {
            const int r = i >> 6, c = i & 63;
            Ks[r * 65 + c] = Kb[(long)(kt * 64 + r) * 64 + c];
            Vs[r * 64 + c] = Vb[(long)(kt * 64 + r) * 64 + c];
        }
        __syncthreads();

        float s[4][4];
        #pragma unroll
        for (int i = 0; i < 4; i++)
            #pragma unroll
            for (int j = 0; j < 4; j++) s[i][j] = 0.f;

        #pragma unroll 8
        for (int k = 0; k < 64; k++) {
            float qa[4], kb2[4];
            #pragma unroll
            for (int i = 0; i < 4; i++) qa[i]  = Qs[(ty * 4 + i) * 64 + k];
            #pragma unroll
            for (int j = 0; j < 4; j++) kb2[j] = Ks[(tx * 4 + j) * 65 + k];
            #pragma unroll
            for (int i = 0; i < 4; i++)
                #pragma unroll
                for (int j = 0; j < 4; j++)
                    s[i][j] = fmaf(qa[i], kb2[j], s[i][j]);
        }

        if (mask) {
            #pragma unroll
            for (int i = 0; i < 4; i++)
                #pragma unroll
                for (int j = 0; j < 4; j++)
                    s[i][j] += mask[(long)(q0 + ty * 4 + i) * 512 + kt * 64 + tx * 4 + j];
        }

        #pragma unroll
        for (int i = 0; i < 4; i++) {
            float tm = fmaxf(fmaxf(s[i][0], s[i][1]), fmaxf(s[i][2], s[i][3]));
            #pragma unroll
            for (int off = 8; off >= 1; off >>= 1)
                tm = fmaxf(tm, __shfl_xor_sync(0xffffffffu, tm, off));
            const float newm = fmaxf(mrow[i], tm);
            float sum = 0.f;
            #pragma unroll
            for (int j = 0; j < 4; j++) {
                const float p = __expf(s[i][j] - newm);
                s[i][j] = p; sum += p;
            }
            #pragma unroll
            for (int off = 8; off >= 1; off >>= 1)
                sum += __shfl_xor_sync(0xffffffffu, sum, off);
            const float corr = __expf(mrow[i] - newm);
            lrow[i] = lrow[i] * corr + sum;
            mrow[i] = newm;
            #pragma unroll
            for (int j = 0; j < 4; j++) o[i][j] *= corr;
            #pragma unroll
            for (int j = 0; j < 4; j++)
                Ps[(ty * 4 + i) * 65 + tx * 4 + j] = s[i][j];
        }
        __syncthreads();

        #pragma unroll 8
        for (int kk = 0; kk < 64; kk++) {
            float pa[4], vb[4];
            #pragma unroll
            for (int i = 0; i < 4; i++) pa[i] = Ps[(ty * 4 + i) * 65 + kk];
            #pragma unroll
            for (int j = 0; j < 4; j++) vb[j] = Vs[kk * 64 + tx * 4 + j];
            #pragma unroll
            for (int i = 0; i < 4; i++)
                #pragma unroll
                for (int j = 0; j < 4; j++)
                    o[i][j] = fmaf(pa[i], vb[j], o[i][j]);
        }
    }

    float* Ob = O + (long)b * 512 * 512;
    #pragma unroll
    for (int i = 0; i < 4; i++) {
        const float inv = 1.f / lrow[i];
        float4 v;
        v.x = o[i][0] * inv; v.y = o[i][1] * inv;
        v.z = o[i][2] * inv; v.w = o[i][3] * inv;
        *(float4*)(Ob + (long)(q0 + ty * 4 + i) * 512 + h * 64 + tx * 4) = v;
    }
}

// ---------------------------------------------------------------------------
// Launch sequence (single stream, graph-capturable, allocation-free)
// ---------------------------------------------------------------------------
extern "C" void kernel_launch(void* const* d_in, const int* in_sizes, int n_in,
                              void* d_out, int out_size)
{
    const float* x             = (const float*)d_in[0];
    const float* mask          = (const float*)d_in[1];
    const float* Wq_inter      = (const float*)d_in[2];
    const float* Wk_inter      = (const float*)d_in[3];
    const float* Wv_inter      = (const float*)d_in[4];
    const float* Wq_intra      = (const float*)d_in[5];
    const float* Wk_intra      = (const float*)d_in[6];
    const float* Wv_intra      = (const float*)d_in[7];
    const float* W_proj_in     = (const float*)d_in[8];
    const float* W_proj_out    = (const float*)d_in[9];
    const float* W_split_inter = (const float*)d_in[10];
    const float* W_out_inter   = (const float*)d_in[11];
    const float* W_split_intra = (const float*)d_in[12];
    const float* W_out_intra   = (const float*)d_in[13];
    const float* alpha         = (const float*)d_in[14];
    float* out = (float*)d_out;

    float *wc_in, *wc_out, *xp, *q, *k, *v, *cc, *oi;
    cudaGetSymbolAddress((void**)&wc_in,  g_Wc_in);
    cudaGetSymbolAddress((void**)&wc_out, g_Wc_out);
    cudaGetSymbolAddress((void**)&xp,     g_xp);
    cudaGetSymbolAddress((void**)&q,      g_q);
    cudaGetSymbolAddress((void**)&k,      g_k);
    cudaGetSymbolAddress((void**)&v,      g_v);
    cudaGetSymbolAddress((void**)&cc,     g_cc);
    cudaGetSymbolAddress((void**)&oi,     g_oi);

    cudaFuncSetAttribute(attn_kernel,
                         cudaFuncAttributeMaxDynamicSharedMemorySize, ATTN_SMEM);

    const long MB = 512L * 512L;
    dim3 tb(256);
    dim3 g1(4, 4, 1);
    dim3 gb(4, 4, BATCH);
    dim3 gq(8, 24, BATCH);
    dim3 ga(8, NH, BATCH);

    // Combined weights (tiny 512^3 GEMMs):
    // Wc_in[a,s]  = sum_j W_split_inter[a,j] * W_proj_in[j,s]   (B col-major)
    gemm512<false, true, 0><<<g1, tb>>>(W_split_inter, 0, W_proj_in, 0,
                                        wc_in, 0, nullptr, 0, nullptr);
    // Wc_out[s,c] = sum_j W_proj_out[s,j] * W_out_inter[j,c]
    gemm512<false, true, 0><<<g1, tb>>>(W_proj_out, 0, W_out_inter, 0,
                                        wc_out, 0, nullptr, 0, nullptr);

    // xp[b,r,c] = sum_s x[b,s,r] * Wc_in[c,s]   (A transposed access)
    gemm512<true, false, 0><<<gb, tb>>>(x, MB, wc_in, 0, xp, MB,
                                        nullptr, 0, nullptr);

    // inter-path QKV + attention (tokens = feature axis, no mask)
    qkv_kernel<<<gq, tb>>>(xp, Wq_inter, Wk_inter, Wv_inter, q, k, v);
    attn_kernel<<<ga, tb, ATTN_SMEM>>>(q, k, v, nullptr, cc);

    // out_inter[b,s,d] = sum_k Wc_out[s,k] * concat[b,d,k] + x[b,s,d]
    gemm512<false, false, 1><<<gb, tb>>>(wc_out, 0, cc, MB, oi, MB,
                                         x, MB, nullptr);

    // xi = out_inter @ W_split_intra^T   (reuse xp buffer)
    gemm512<false, false, 0><<<gb, tb>>>(oi, MB, W_split_intra, 0, xp, MB,
                                         nullptr, 0, nullptr);

    // intra-path QKV + attention (tokens = sequence, mask added)
    qkv_kernel<<<gq, tb>>>(xp, Wq_intra, Wk_intra, Wv_intra, q, k, v);
    attn_kernel<<<ga, tb, ATTN_SMEM>>>(q, k, v, mask, cc);

    // final: out = (1-sigmoid(alpha)) * (cc @ W_out_intra^T) + sigmoid(alpha) * out_inter
    gemm512<false, false, 2><<<gb, tb>>>(cc, MB, W_out_intra, 0, out, MB,
                                         oi, MB, alpha);
}

// round 3
// speedup vs baseline: 1.0006x; 1.0006x over previous
#include <cuda_runtime.h>

// Problem constants
static constexpr int BATCH = 32;
static constexpr int NH    = 8;
// all big matrices are 512x512 with ld 512

// ---------------------------------------------------------------------------
// Scratch (static __device__ arrays: allocation-free per harness rules)
// ---------------------------------------------------------------------------
__device__ float g_Wc_in [512 * 512];
__device__ float g_Wc_out[512 * 512];
__device__ float g_xp    [(long)BATCH * 512 * 512];
__device__ float g_q     [(long)BATCH * NH * 512 * 64];
__device__ float g_k     [(long)BATCH * NH * 512 * 64];
__device__ float g_v     [(long)BATCH * NH * 512 * 64];
__device__ float g_cc    [(long)BATCH * 512 * 512];
__device__ float g_oi    [(long)BATCH * 512 * 512];

// ---------------------------------------------------------------------------
// Generic batched 512x512x512 SGEMM:  C[b][m][n] = sum_k opA[m,k] * opB[n,k]
//   AT=false: A[m*512+k] (row-major, K contiguous)   AT=true: A[k*512+m]
//   BT=false: B[n*512+k]                             BT=true: B[k*512+n]
//   EPI 0: C=acc   1: C=acc+R   2: C=(1-a)*acc + a*R, a=sigmoid(*alpha_ptr)
// Tile 128x128, BK=8, 256 threads, 8x8 microtile per thread.
// ---------------------------------------------------------------------------
template<bool AT, bool BT, int EPI>
__global__ __launch_bounds__(256) void gemm512(
    const float* __restrict__ A, long sA,
    const float* __restrict__ B, long sB,
    float* __restrict__ C, long sC,
    const float* __restrict__ R, long sR,
    const float* __restrict__ alpha_ptr)
{
    __shared__ float As[8][128];
    __shared__ float Bs[8][128];
    const int bN = blockIdx.x * 128;
    const int bM = blockIdx.y * 128;
    const int bz = blockIdx.z;
    A += (long)bz * sA;
    B += (long)bz * sB;
    C += (long)bz * sC;
    if (EPI != 0) R += (long)bz * sR;

    const int tid  = threadIdx.x;
    const int tx   = tid & 15;
    const int ty   = tid >> 4;
    const int lk   = tid >> 5;          // T layout: k row of tile
    const int lm   = (tid & 31) << 2;   // T layout: 4-float col offset
    const int lrow = tid >> 1;          // N layout: row within tile
    const int lq   = (tid & 1) << 2;    // N layout: 4-float k offset

    float acc[8][8];
    #pragma unroll
    for (int i = 0; i < 8; i++)
        #pragma unroll
        for (int j = 0; j < 8; j++) acc[i][j] = 0.f;

    for (int kt = 0; kt < 64; kt++) {
        const int k0 = kt * 8;
        float4 ar, br;
        if (AT) ar = *(const float4*)(A + (long)(k0 + lk) * 512 + bM + lm);
        else    ar = *(const float4*)(A + (long)(bM + lrow) * 512 + k0 + lq);
        if (BT) br = *(const float4*)(B + (long)(k0 + lk) * 512 + bN + lm);
        else    br = *(const float4*)(B + (long)(bN + lrow) * 512 + k0 + lq);
        __syncthreads();
        if (AT) { *(float4*)&As[lk][lm] = ar; }
        else {
            As[lq + 0][lrow] = ar.x; As[lq + 1][lrow] = ar.y;
            As[lq + 2][lrow] = ar.z; As[lq + 3][lrow] = ar.w;
        }
        if (BT) { *(float4*)&Bs[lk][lm] = br; }
        else {
            Bs[lq + 0][lrow] = br.x; Bs[lq + 1][lrow] = br.y;
            Bs[lq + 2][lrow] = br.z; Bs[lq + 3][lrow] = br.w;
        }
        __syncthreads();
        #pragma unroll
        for (int k = 0; k < 8; k++) {
            float4 a0 = *(const float4*)&As[k][ty * 4];
            float4 a1 = *(const float4*)&As[k][ty * 4 + 64];
            float4 b0 = *(const float4*)&Bs[k][tx * 4];
            float4 b1 = *(const float4*)&Bs[k][tx * 4 + 64];
            float av[8] = {a0.x, a0.y, a0.z, a0.w, a1.x, a1.y, a1.z, a1.w};
            float bv[8] = {b0.x, b0.y, b0.z, b0.w, b1.x, b1.y, b1.z, b1.w};
            #pragma unroll
            for (int i = 0; i < 8; i++)
                #pragma unroll
                for (int j = 0; j < 8; j++)
                    acc[i][j] = fmaf(av[i], bv[j], acc[i][j]);
        }
    }

    float ab = 0.f;
    if (EPI == 2) ab = 1.f / (1.f + expf(-alpha_ptr[0]));
    #pragma unroll
    for (int i = 0; i < 8; i++) {
        const int m = bM + ((i >> 2) << 6) + ty * 4 + (i & 3);
        #pragma unroll
        for (int cg = 0; cg < 2; cg++) {
            const int n = bN + cg * 64 + tx * 4;
            float4 v;
            v.x = acc[i][cg * 4 + 0]; v.y = acc[i][cg * 4 + 1];
            v.z = acc[i][cg * 4 + 2]; v.w = acc[i][cg * 4 + 3];
            if (EPI == 1) {
                float4 r = *(const float4*)(R + (long)m * 512 + n);
                v.x += r.x; v.y += r.y; v.z += r.z; v.w += r.w;
            } else if (EPI == 2) {
                float4 r = *(const float4*)(R + (long)m * 512 + n);
                v.x = (1.f - ab) * v.x + ab * r.x;
                v.y = (1.f - ab) * v.y + ab * r.y;
                v.z = (1.f - ab) * v.z + ab * r.z;
                v.w = (1.f - ab) * v.w + ab * r.w;
            }
            *(float4*)(C + (long)m * 512 + n) = v;
        }
    }
}

// ---------------------------------------------------------------------------
// Per-head projection: O[b,h,n,e] = sum_d X[b, n, h*64+d] * W[h, e, d]
// grid: (8 row-tiles, 24 = which*8+h, 32 batch), 256 threads.
// Output layout: [b*NH+h][512][64]
// ---------------------------------------------------------------------------
__global__ __launch_bounds__(256) void qkv_kernel(
    const float* __restrict__ X,
    const float* __restrict__ Wq, const float* __restrict__ Wk,
    const float* __restrict__ Wv,
    float* __restrict__ Q, float* __restrict__ K, float* __restrict__ V)
{
    __shared__ float Xs[64][64];
    __shared__ float Ws[64][65];
    const int r0    = blockIdx.x * 64;
    const int which = blockIdx.y >> 3;
    const int h     = blockIdx.y & 7;
    const int b     = blockIdx.z;
    const float* W  = (which == 0) ? Wq : (which == 1) ? Wk : Wv;
    float* O        = (which == 0) ? Q  : (which == 1) ? K  : V;
    const int tid = threadIdx.x;
    const int tx = tid & 15, ty = tid >> 4;
    const float* Xb = X + (long)b * 512 * 512;

    for (int i = tid; i < 4096; i += 256) {
        const int r = i >> 6, c = i & 63;
        Xs[r][c] = Xb[(long)(r0 + r) * 512 + h * 64 + c];
        Ws[r][c] = W[h * 4096 + i];   // [e][d] row-major
    }
    __syncthreads();

    float acc[4][4];
    #pragma unroll
    for (int i = 0; i < 4; i++)
        #pragma unroll
        for (int j = 0; j < 4; j++) acc[i][j] = 0.f;

    #pragma unroll 8
    for (int k = 0; k < 64; k++) {
        float xv[4], wv[4];
        #pragma unroll
        for (int i = 0; i < 4; i++) xv[i] = Xs[ty * 4 + i][k];
        #pragma unroll
        for (int j = 0; j < 4; j++) wv[j] = Ws[tx * 4 + j][k];
        #pragma unroll
        for (int i = 0; i < 4; i++)
            #pragma unroll
            for (int j = 0; j < 4; j++)
                acc[i][j] = fmaf(xv[i], wv[j], acc[i][j]);
    }

    float* Ob = O + (long)(b * NH + h) * 512 * 64;
    #pragma unroll
    for (int i = 0; i < 4; i++) {
        float4 v;
        v.x = acc[i][0]; v.y = acc[i][1]; v.z = acc[i][2]; v.w = acc[i][3];
        *(float4*)(Ob + (long)(r0 + ty * 4 + i) * 64 + tx * 4) = v;
    }
}

// ---------------------------------------------------------------------------
// Fused flash-style attention per (b, h, 64-row q tile).
// Q/K/V layout [b*NH+h][512][64]. Output written head-concatenated:
// O[b][n][h*64+e]. Online softmax (running max / sum), P staged via smem.
// Q is pre-scaled by 1/sqrt(64); mask (optional) added post-scale (matches ref).
// ---------------------------------------------------------------------------
static constexpr int ATTN_SMEM = (64 * 64 + 64 * 65 + 64 * 64 + 64 * 65) * 4;

__global__ __launch_bounds__(256) void attn_kernel(
    const float* __restrict__ Q, const float* __restrict__ K,
    const float* __restrict__ V, const float* __restrict__ mask,
    float* __restrict__ O)
{
    extern __shared__ float sm[];
    float* Qs = sm;                // [64][64]
    float* Ks = Qs + 64 * 64;      // [64][65] (padded)
    float* Vs = Ks + 64 * 65;      // [64][64]
    float* Ps = Vs + 64 * 64;      // [64][65] (padded)

    const int q0 = blockIdx.x * 64;
    const int h  = blockIdx.y;
    const int b  = blockIdx.z;
    const long base = (long)(b * NH + h) * 512 * 64;
    const float* Qb = Q + base;
    const float* Kb = K + base;
    const float* Vb = V + base;
    const int tid = threadIdx.x;
    const int tx = tid & 15, ty = tid >> 4;

    for (int i = tid; i < 4096; i += 256) {
        const int r = i >> 6, c = i & 63;
        Qs[r * 64 + c] = Qb[(long)(q0 + r) * 64 + c] * 0.125f; // 1/sqrt(64)
    }

    float mrow[4], lrow[4], o[4][4];
    #pragma unroll
    for (int i = 0; i < 4; i++) {
        mrow[i] = -1e30f; lrow[i] = 0.f;
        #pragma unroll
        for (int j = 0; j < 4; j++) o[i][j] = 0.f;
    }

    for (int kt = 0; kt < 8; kt++) {
        __syncthreads();   // protect Ks/Vs/Ps from previous iteration's readers
        for (int i = tid; i < 4096; i += 256) {
            const int r = i >> 6, c = i & 63;
            Ks[r * 65 + c] = Kb[(long)(kt * 64 + r) * 64 + c];
            Vs[r * 64 + c] = Vb[(long)(kt * 64 + r) * 64 + c];
        }
        __syncthreads();

        float s[4][4];
        #pragma unroll
        for (int i = 0; i < 4; i++)
            #pragma unroll
            for (int j = 0; j < 4; j++) s[i][j] = 0.f;

        #pragma unroll 8
        for (int k = 0; k < 64; k++) {
            float qa[4], kb2[4];
            #pragma unroll
            for (int i = 0; i < 4; i++) qa[i]  = Qs[(ty * 4 + i) * 64 + k];
            #pragma unroll
            for (int j = 0; j < 4; j++) kb2[j] = Ks[(tx * 4 + j) * 65 + k];
            #pragma unroll
            for (int i = 0; i < 4; i++)
                #pragma unroll
                for (int j = 0; j < 4; j++)
                    s[i][j] = fmaf(qa[i], kb2[j], s[i][j]);
        }

        if (mask) {
            #pragma unroll
            for (int i = 0; i < 4; i++)
                #pragma unroll
                for (int j = 0; j < 4; j++)
                    s[i][j] += mask[(long)(q0 + ty * 4 + i) * 512 + kt * 64 + tx * 4 + j];
        }

        #pragma unroll
        for (int i = 0; i < 4; i++) {
            float tm = fmaxf(fmaxf(s[i][0], s[i][1]), fmaxf(s[i][2], s[i][3]));
            #pragma unroll
            for (int off = 8; off >= 1; off >>= 1)
                tm = fmaxf(tm, __shfl_xor_sync(0xffffffffu, tm, off));
            const float newm = fmaxf(mrow[i], tm);
            float sum = 0.f;
            #pragma unroll
            for (int j = 0; j < 4; j++) {
                const float p = __expf(s[i][j] - newm);
                s[i][j] = p; sum += p;
            }
            #pragma unroll
            for (int off = 8; off >= 1; off >>= 1)
                sum += __shfl_xor_sync(0xffffffffu, sum, off);
            const float corr = __expf(mrow[i] - newm);
            lrow[i] = lrow[i] * corr + sum;
            mrow[i] = newm;
            #pragma unroll
            for (int j = 0; j < 4; j++) o[i][j] *= corr;
            #pragma unroll
            for (int j = 0; j < 4; j++)
                Ps[(ty * 4 + i) * 65 + tx * 4 + j] = s[i][j];
        }
        __syncthreads();

        #pragma unroll 8
        for (int kk = 0; kk < 64; kk++) {
            float pa[4], vb[4];
            #pragma unroll
            for (int i = 0; i < 4; i++) pa[i] = Ps[(ty * 4 + i) * 65 + kk];
            #pragma unroll
            for (int j = 0; j < 4; j++) vb[j] = Vs[kk * 64 + tx * 4 + j];
            #pragma unroll
            for (int i = 0; i < 4; i++)
                #pragma unroll
                for (int j = 0; j < 4; j++)
                    o[i][j] = fmaf(pa[i], vb[j], o[i][j]);
        }
    }

    float* Ob = O + (long)b * 512 * 512;
    #pragma unroll
    for (int i = 0; i < 4; i++) {
        const float inv = 1.f / lrow[i];
        float4 v;
        v.x = o[i][0] * inv; v.y = o[i][1] * inv;
        v.z = o[i][2] * inv; v.w = o[i][3] * inv;
        *(float4*)(Ob + (long)(q0 + ty * 4 + i) * 512 + h * 64 + tx * 4) = v;
    }
}

// ---------------------------------------------------------------------------
// Launch sequence (single stream, graph-capturable, allocation-free)
// ---------------------------------------------------------------------------
extern "C" void kernel_launch(void* const* d_in, const int* in_sizes, int n_in,
                              void* d_out, int out_size)
{
    const float* x             = (const float*)d_in[0];
    const float* mask          = (const float*)d_in[1];
    const float* Wq_inter      = (const float*)d_in[2];
    const float* Wk_inter      = (const float*)d_in[3];
    const float* Wv_inter      = (const float*)d_in[4];
    const float* Wq_intra      = (const float*)d_in[5];
    const float* Wk_intra      = (const float*)d_in[6];
    const float* Wv_intra      = (const float*)d_in[7];
    const float* W_proj_in     = (const float*)d_in[8];
    const float* W_proj_out    = (const float*)d_in[9];
    const float* W_split_inter = (const float*)d_in[10];
    const float* W_out_inter   = (const float*)d_in[11];
    const float* W_split_intra = (const float*)d_in[12];
    const float* W_out_intra   = (const float*)d_in[13];
    const float* alpha         = (const float*)d_in[14];
    float* out = (float*)d_out;

    float *wc_in, *wc_out, *xp, *q, *k, *v, *cc, *oi;
    cudaGetSymbolAddress((void**)&wc_in,  g_Wc_in);
    cudaGetSymbolAddress((void**)&wc_out, g_Wc_out);
    cudaGetSymbolAddress((void**)&xp,     g_xp);
    cudaGetSymbolAddress((void**)&q,      g_q);
    cudaGetSymbolAddress((void**)&k,      g_k);
    cudaGetSymbolAddress((void**)&v,      g_v);
    cudaGetSymbolAddress((void**)&cc,     g_cc);
    cudaGetSymbolAddress((void**)&oi,     g_oi);

    cudaFuncSetAttribute(attn_kernel,
                         cudaFuncAttributeMaxDynamicSharedMemorySize, ATTN_SMEM);

    const long MB = 512L * 512L;
    dim3 tb(256);
    dim3 g1(4, 4, 1);
    dim3 gb(4, 4, BATCH);
    dim3 gq(8, 24, BATCH);
    dim3 ga(8, NH, BATCH);

    // Combined weights (tiny 512^3 GEMMs):
    // Wc_in[a,s]  = sum_j W_split_inter[a,j] * W_proj_in[j,s]   (B col-major)
    gemm512<false, true, 0><<<g1, tb>>>(W_split_inter, 0, W_proj_in, 0,
                                        wc_in, 0, nullptr, 0, nullptr);
    // Wc_out[s,c] = sum_j W_proj_out[s,j] * W_out_inter[j,c]
    gemm512<false, true, 0><<<g1, tb>>>(W_proj_out, 0, W_out_inter, 0,
                                        wc_out, 0, nullptr, 0, nullptr);

    // xp[b,r,c] = sum_s x[b,s,r] * Wc_in[c,s]   (A transposed access)
    gemm512<true, false, 0><<<gb, tb>>>(x, MB, wc_in, 0, xp, MB,
                                        nullptr, 0, nullptr);

    // inter-path QKV + attention (tokens = feature axis, no mask)
    qkv_kernel<<<gq, tb>>>(xp, Wq_inter, Wk_inter, Wv_inter, q, k, v);
    attn_kernel<<<ga, tb, ATTN_SMEM>>>(q, k, v, nullptr, cc);

    // out_inter[b,s,d] = sum_k Wc_out[s,k] * concat[b,d,k] + x[b,s,d]
    gemm512<false, false, 1><<<gb, tb>>>(wc_out, 0, cc, MB, oi, MB,
                                         x, MB, nullptr);

    // xi = out_inter @ W_split_intra^T   (reuse xp buffer)
    gemm512<false, false, 0><<<gb, tb>>>(oi, MB, W_split_intra, 0, xp, MB,
                                         nullptr, 0, nullptr);

    // intra-path QKV + attention (tokens = sequence, mask added)
    qkv_kernel<<<gq, tb>>>(xp, Wq_intra, Wk_intra, Wv_intra, q, k, v);
    attn_kernel<<<ga, tb, ATTN_SMEM>>>(q, k, v, mask, cc);

    // final: out = (1-sigmoid(alpha)) * (cc @ W_out_intra^T) + sigmoid(alpha) * out_inter
    gemm512<false, false, 2><<<gb, tb>>>(cc, MB, W_out_intra, 0, out, MB,
                                         oi, MB, alpha);
}

// round 6
// speedup vs baseline: 1.2231x; 1.2224x over previous
#include <cuda_runtime.h>
#include <cuda_bf16.h>
#include <cstdint>

static constexpr int BATCH = 32;
static constexpr int NH    = 8;

// ---------------------------------------------------------------------------
// Scratch (static __device__ arrays: allocation-free per harness rules)
// ---------------------------------------------------------------------------
__device__ float g_Wc_in [512 * 512];
__device__ float g_Wc_out[512 * 512];
__device__ float g_xp    [(long)BATCH * 512 * 512];
__device__ float g_q     [(long)BATCH * NH * 512 * 64];
__device__ float g_k     [(long)BATCH * NH * 512 * 64];
__device__ float g_v     [(long)BATCH * NH * 512 * 64];
__device__ float g_cc    [(long)BATCH * 512 * 512];
__device__ float g_oi    [(long)BATCH * 512 * 512];

// bf16 hi/lo split copies for tensor-core GEMMs
__device__ __nv_bfloat16 g_xT_hi[(long)BATCH * 512 * 512];
__device__ __nv_bfloat16 g_xT_lo[(long)BATCH * 512 * 512];
__device__ __nv_bfloat16 g_cc_hi[(long)BATCH * 512 * 512];
__device__ __nv_bfloat16 g_cc_lo[(long)BATCH * 512 * 512];
__device__ __nv_bfloat16 g_oi_hi[(long)BATCH * 512 * 512];
__device__ __nv_bfloat16 g_oi_lo[(long)BATCH * 512 * 512];
__device__ __nv_bfloat16 g_wcin_hi[512 * 512];
__device__ __nv_bfloat16 g_wcin_lo[512 * 512];
__device__ __nv_bfloat16 g_wcout_hi[512 * 512];
__device__ __nv_bfloat16 g_wcout_lo[512 * 512];
__device__ __nv_bfloat16 g_wsi_hi[512 * 512];
__device__ __nv_bfloat16 g_wsi_lo[512 * 512];
__device__ __nv_bfloat16 g_woi_hi[512 * 512];
__device__ __nv_bfloat16 g_woi_lo[512 * 512];

// ---------------------------------------------------------------------------
// mma.sync m16n8k16 bf16 (sm_80+ baseline; works on plain sm_100 target)
// ---------------------------------------------------------------------------
__device__ __forceinline__ void mma16816(float* c, const uint32_t* a,
                                         uint32_t b0, uint32_t b1) {
    asm volatile(
        "mma.sync.aligned.m16n8k16.row.col.f32.bf16.bf16.f32 "
        "{%0,%1,%2,%3}, {%4,%5,%6,%7}, {%8,%9}, {%0,%1,%2,%3};"
        : "+f"(c[0]), "+f"(c[1]), "+f"(c[2]), "+f"(c[3])
        : "r"(a[0]), "r"(a[1]), "r"(a[2]), "r"(a[3]), "r"(b0), "r"(b1));
}

// ---------------------------------------------------------------------------
// fp32 -> bf16 hi/lo split (vectorized, no transpose)
// ---------------------------------------------------------------------------
__global__ __launch_bounds__(256) void split_kernel(
    const float4* __restrict__ in, __nv_bfloat16* __restrict__ hi,
    __nv_bfloat16* __restrict__ lo, long n4)
{
    long i = (long)blockIdx.x * 256 + threadIdx.x;
    if (i >= n4) return;
    float4 v = in[i];
    float f[4] = {v.x, v.y, v.z, v.w};
    __nv_bfloat16 h[4], l[4];
    #pragma unroll
    for (int j = 0; j < 4; j++) {
        h[j] = __float2bfloat16_rn(f[j]);
        l[j] = __float2bfloat16_rn(f[j] - __bfloat162float(h[j]));
    }
    *(uint2*)(hi + i * 4) = *(uint2*)h;
    *(uint2*)(lo + i * 4) = *(uint2*)l;
}

// transpose + split for x: out[b][d][s] = x[b][s][d]
__global__ __launch_bounds__(256) void transpose_split_kernel(
    const float* __restrict__ in, __nv_bfloat16* __restrict__ hi,
    __nv_bfloat16* __restrict__ lo)
{
    __shared__ float t[32][33];
    const int b = blockIdx.z;
    const int s0 = blockIdx.x * 32, d0 = blockIdx.y * 32;
    const long base = (long)b * 512 * 512;
    const int tx = threadIdx.x, ty = threadIdx.y;
    #pragma unroll
    for (int i = ty; i < 32; i += 8)
        t[i][tx] = in[base + (long)(s0 + i) * 512 + d0 + tx];
    __syncthreads();
    #pragma unroll
    for (int i = ty; i < 32; i += 8) {
        float v = t[tx][i];   // = in[s0+tx][d0+i]
        __nv_bfloat16 h = __float2bfloat16_rn(v);
        __nv_bfloat16 l = __float2bfloat16_rn(v - __bfloat162float(h));
        long o = base + (long)(d0 + i) * 512 + s0 + tx;
        hi[o] = h; lo[o] = l;
    }
}

// ---------------------------------------------------------------------------
// Tensor-core batched GEMM: C[b][m][n] = sum_k A[b][m][k] * B[b][n][k]
// A/B as bf16 hi/lo pairs (row-major, ld=512). 3-term split accumulation.
// 128x128 CTA tile, BK=64, 8 warps each 32(m) x 64(n).
// EPI 0: C=acc  1: C=acc+R  2: C=(1-a)*acc + a*R, a=sigmoid(*alpha_ptr)
// ---------------------------------------------------------------------------
static constexpr int SK = 72;                       // smem row stride (elems)
static constexpr int TCG_SMEM = 4 * 128 * SK * 2;   // 73728 bytes

__device__ __forceinline__ void load_tile(
    __nv_bfloat16* __restrict__ dst, const __nv_bfloat16* __restrict__ src,
    int row0, int k0, int tid)
{
    #pragma unroll
    for (int it = 0; it < 4; it++) {
        int idx = tid + it * 256;          // 0..1023
        int r  = idx >> 3;
        int c8 = idx & 7;
        uint4 v = *(const uint4*)(src + (long)(row0 + r) * 512 + k0 + c8 * 8);
        *(uint4*)(dst + r * SK + c8 * 8) = v;
    }
}

template<int EPI>
__global__ __launch_bounds__(256) void tc_gemm(
    const __nv_bfloat16* __restrict__ Ahi, const __nv_bfloat16* __restrict__ Alo, long sA,
    const __nv_bfloat16* __restrict__ Bhi, const __nv_bfloat16* __restrict__ Blo, long sB,
    float* __restrict__ C, long sC,
    const float* __restrict__ R, long sR,
    const float* __restrict__ alpha_ptr)
{
    extern __shared__ __nv_bfloat16 sm[];
    __nv_bfloat16* sAh = sm;
    __nv_bfloat16* sAl = sAh + 128 * SK;
    __nv_bfloat16* sBh = sAl + 128 * SK;
    __nv_bfloat16* sBl = sBh + 128 * SK;

    const int tid  = threadIdx.x;
    const int lane = tid & 31;
    const int wid  = tid >> 5;
    const int g    = lane >> 2;       // 0..7
    const int tg   = lane & 3;        // 0..3
    const int wm   = (wid >> 1) * 32; // warp row offset in tile
    const int wn   = (wid & 1) * 64;  // warp col offset in tile

    const int bN = blockIdx.x * 128;
    const int bM = blockIdx.y * 128;
    const int bz = blockIdx.z;
    Ahi += (long)bz * sA; Alo += (long)bz * sA;
    Bhi += (long)bz * sB; Blo += (long)bz * sB;
    C   += (long)bz * sC;
    if (EPI != 0) R += (long)bz * sR;

    float acc[2][8][4];
    #pragma unroll
    for (int i = 0; i < 2; i++)
        #pragma unroll
        for (int j = 0; j < 8; j++)
            #pragma unroll
            for (int q = 0; q < 4; q++) acc[i][j][q] = 0.f;

    for (int t = 0; t < 8; t++) {
        const int k0 = t * 64;
        __syncthreads();
        load_tile(sAh, Ahi, bM, k0, tid);
        load_tile(sAl, Alo, bM, k0, tid);
        load_tile(sBh, Bhi, bN, k0, tid);
        load_tile(sBl, Blo, bN, k0, tid);
        __syncthreads();

        #pragma unroll
        for (int ks = 0; ks < 4; ks++) {
            const int kb = ks * 16;
            uint32_t ah[2][4], al[2][4];
            #pragma unroll
            for (int mi = 0; mi < 2; mi++) {
                const int r0 = wm + mi * 16 + g;
                ah[mi][0] = *(const uint32_t*)(sAh + (r0     ) * SK + kb + tg * 2);
                ah[mi][1] = *(const uint32_t*)(sAh + (r0 +  8) * SK + kb + tg * 2);
                ah[mi][2] = *(const uint32_t*)(sAh + (r0     ) * SK + kb + tg * 2 + 8);
                ah[mi][3] = *(const uint32_t*)(sAh + (r0 +  8) * SK + kb + tg * 2 + 8);
                al[mi][0] = *(const uint32_t*)(sAl + (r0     ) * SK + kb + tg * 2);
                al[mi][1] = *(const uint32_t*)(sAl + (r0 +  8) * SK + kb + tg * 2);
                al[mi][2] = *(const uint32_t*)(sAl + (r0     ) * SK + kb + tg * 2 + 8);
                al[mi][3] = *(const uint32_t*)(sAl + (r0 +  8) * SK + kb + tg * 2 + 8);
            }
            #pragma unroll
            for (int nj = 0; nj < 8; nj++) {
                const int nr = wn + nj * 8 + g;
                const uint32_t bh0 = *(const uint32_t*)(sBh + nr * SK + kb + tg * 2);
                const uint32_t bh1 = *(const uint32_t*)(sBh + nr * SK + kb + tg * 2 + 8);
                const uint32_t bl0 = *(const uint32_t*)(sBl + nr * SK + kb + tg * 2);
                const uint32_t bl1 = *(const uint32_t*)(sBl + nr * SK + kb + tg * 2 + 8);
                #pragma unroll
                for (int mi = 0; mi < 2; mi++) {
                    mma16816(acc[mi][nj], ah[mi], bh0, bh1);
                    mma16816(acc[mi][nj], ah[mi], bl0, bl1);
                    mma16816(acc[mi][nj], al[mi], bh0, bh1);
                }
            }
        }
    }

    float ab = 0.f;
    if (EPI == 2) ab = 1.f / (1.f + expf(-alpha_ptr[0]));
    #pragma unroll
    for (int mi = 0; mi < 2; mi++) {
        #pragma unroll
        for (int nj = 0; nj < 8; nj++) {
            const int row = bM + wm + mi * 16 + g;
            const int col = bN + wn + nj * 8 + tg * 2;
            float2 v0 = {acc[mi][nj][0], acc[mi][nj][1]};
            float2 v1 = {acc[mi][nj][2], acc[mi][nj][3]};
            if (EPI == 1) {
                float2 r0 = *(const float2*)(R + (long)row * 512 + col);
                float2 r1 = *(const float2*)(R + (long)(row + 8) * 512 + col);
                v0.x += r0.x; v0.y += r0.y; v1.x += r1.x; v1.y += r1.y;
            } else if (EPI == 2) {
                float2 r0 = *(const float2*)(R + (long)row * 512 + col);
                float2 r1 = *(const float2*)(R + (long)(row + 8) * 512 + col);
                v0.x = (1.f - ab) * v0.x + ab * r0.x;
                v0.y = (1.f - ab) * v0.y + ab * r0.y;
                v1.x = (1.f - ab) * v1.x + ab * r1.x;
                v1.y = (1.f - ab) * v1.y + ab * r1.y;
            }
            *(float2*)(C + (long)row * 512 + col) = v0;
            *(float2*)(C + (long)(row + 8) * 512 + col) = v1;
        }
    }
}

// ---------------------------------------------------------------------------
// fp32 SGEMM (only used for the two tiny weight-combine GEMMs)
// C[m][n] = sum_k A[m,k] * B[k,n]
// ---------------------------------------------------------------------------
__global__ __launch_bounds__(256) void gemm512_nt(
    const float* __restrict__ A, const float* __restrict__ B,
    float* __restrict__ C)
{
    __shared__ float As[8][128];
    __shared__ float Bs[8][128];
    const int bN = blockIdx.x * 128;
    const int bM = blockIdx.y * 128;
    const int tid  = threadIdx.x;
    const int tx   = tid & 15;
    const int ty   = tid >> 4;
    const int lk   = tid >> 5;
    const int lm   = (tid & 31) << 2;
    const int lrow = tid >> 1;
    const int lq   = (tid & 1) << 2;

    float acc[8][8];
    #pragma unroll
    for (int i = 0; i < 8; i++)
        #pragma unroll
        for (int j = 0; j < 8; j++) acc[i][j] = 0.f;

    for (int kt = 0; kt < 64; kt++) {
        const int k0 = kt * 8;
        float4 ar = *(const float4*)(A + (long)(bM + lrow) * 512 + k0 + lq);
        float4 br = *(const float4*)(B + (long)(k0 + lk) * 512 + bN + lm);
        __syncthreads();
        As[lq + 0][lrow] = ar.x; As[lq + 1][lrow] = ar.y;
        As[lq + 2][lrow] = ar.z; As[lq + 3][lrow] = ar.w;
        *(float4*)&Bs[lk][lm] = br;
        __syncthreads();
        #pragma unroll
        for (int k = 0; k < 8; k++) {
            float4 a0 = *(const float4*)&As[k][ty * 4];
            float4 a1 = *(const float4*)&As[k][ty * 4 + 64];
            float4 b0 = *(const float4*)&Bs[k][tx * 4];
            float4 b1 = *(const float4*)&Bs[k][tx * 4 + 64];
            float av[8] = {a0.x, a0.y, a0.z, a0.w, a1.x, a1.y, a1.z, a1.w};
            float bv[8] = {b0.x, b0.y, b0.z, b0.w, b1.x, b1.y, b1.z, b1.w};
            #pragma unroll
            for (int i = 0; i < 8; i++)
                #pragma unroll
                for (int j = 0; j < 8; j++)
                    acc[i][j] = fmaf(av[i], bv[j], acc[i][j]);
        }
    }
    #pragma unroll
    for (int i = 0; i < 8; i++) {
        const int m = bM + ((i >> 2) << 6) + ty * 4 + (i & 3);
        #pragma unroll
        for (int cg = 0; cg < 2; cg++) {
            const int n = bN + cg * 64 + tx * 4;
            float4 v;
            v.x = acc[i][cg * 4 + 0]; v.y = acc[i][cg * 4 + 1];
            v.z = acc[i][cg * 4 + 2]; v.w = acc[i][cg * 4 + 3];
            *(float4*)(C + (long)m * 512 + n) = v;
        }
    }
}

// ---------------------------------------------------------------------------
// Per-head projection: O[b,h,n,e] = sum_d X[b, n, h*64+d] * W[h, e, d]
// ---------------------------------------------------------------------------
__global__ __launch_bounds__(256) void qkv_kernel(
    const float* __restrict__ X,
    const float* __restrict__ Wq, const float* __restrict__ Wk,
    const float* __restrict__ Wv,
    float* __restrict__ Q, float* __restrict__ K, float* __restrict__ V)
{
    __shared__ float Xs[64][64];
    __shared__ float Ws[64][65];
    const int r0    = blockIdx.x * 64;
    const int which = blockIdx.y >> 3;
    const int h     = blockIdx.y & 7;
    const int b     = blockIdx.z;
    const float* W  = (which == 0) ? Wq : (which == 1) ? Wk : Wv;
    float* O        = (which == 0) ? Q  : (which == 1) ? K  : V;
    const int tid = threadIdx.x;
    const int tx = tid & 15, ty = tid >> 4;
    const float* Xb = X + (long)b * 512 * 512;

    for (int i = tid; i < 4096; i += 256) {
        const int r = i >> 6, c = i & 63;
        Xs[r][c] = Xb[(long)(r0 + r) * 512 + h * 64 + c];
        Ws[r][c] = W[h * 4096 + i];
    }
    __syncthreads();

    float acc[4][4];
    #pragma unroll
    for (int i = 0; i < 4; i++)
        #pragma unroll
        for (int j = 0; j < 4; j++) acc[i][j] = 0.f;

    #pragma unroll 8
    for (int k = 0; k < 64; k++) {
        float xv[4], wv[4];
        #pragma unroll
        for (int i = 0; i < 4; i++) xv[i] = Xs[ty * 4 + i][k];
        #pragma unroll
        for (int j = 0; j < 4; j++) wv[j] = Ws[tx * 4 + j][k];
        #pragma unroll
        for (int i = 0; i < 4; i++)
            #pragma unroll
            for (int j = 0; j < 4; j++)
                acc[i][j] = fmaf(xv[i], wv[j], acc[i][j]);
    }

    float* Ob = O + (long)(b * NH + h) * 512 * 64;
    #pragma unroll
    for (int i = 0; i < 4; i++) {
        float4 v;
        v.x = acc[i][0]; v.y = acc[i][1]; v.z = acc[i][2]; v.w = acc[i][3];
        *(float4*)(Ob + (long)(r0 + ty * 4 + i) * 64 + tx * 4) = v;
    }
}

// ---------------------------------------------------------------------------
// Fused flash-style attention (unchanged)
// ---------------------------------------------------------------------------
static constexpr int ATTN_SMEM = (64 * 64 + 64 * 65 + 64 * 64 + 64 * 65) * 4;

__global__ __launch_bounds__(256) void attn_kernel(
    const float* __restrict__ Q, const float* __restrict__ K,
    const float* __restrict__ V, const float* __restrict__ mask,
    float* __restrict__ O)
{
    extern __shared__ float smf[];
    float* Qs = smf;
    float* Ks = Qs + 64 * 64;
    float* Vs = Ks + 64 * 65;
    float* Ps = Vs + 64 * 64;

    const int q0 = blockIdx.x * 64;
    const int h  = blockIdx.y;
    const int b  = blockIdx.z;
    const long base = (long)(b * NH + h) * 512 * 64;
    const float* Qb = Q + base;
    const float* Kb = K + base;
    const float* Vb = V + base;
    const int tid = threadIdx.x;
    const int tx = tid & 15, ty = tid >> 4;

    for (int i = tid; i < 4096; i += 256) {
        const int r = i >> 6, c = i & 63;
        Qs[r * 64 + c] = Qb[(long)(q0 + r) * 64 + c] * 0.125f;
    }

    float mrow[4], lrow[4], o[4][4];
    #pragma unroll
    for (int i = 0; i < 4; i++) {
        mrow[i] = -1e30f; lrow[i] = 0.f;
        #pragma unroll
        for (int j = 0; j < 4; j++) o[i][j] = 0.f;
    }

    for (int kt = 0; kt < 8; kt++) {
        __syncthreads();
        for (int i = tid; i < 4096; i += 256) {
            const int r = i >> 6, c = i & 63;
            Ks[r * 65 + c] = Kb[(long)(kt * 64 + r) * 64 + c];
            Vs[r * 64 + c] = Vb[(long)(kt * 64 + r) * 64 + c];
        }
        __syncthreads();

        float s[4][4];
        #pragma unroll
        for (int i = 0; i < 4; i++)
            #pragma unroll
            for (int j = 0; j < 4; j++) s[i][j] = 0.f;

        #pragma unroll 8
        for (int k = 0; k < 64; k++) {
            float qa[4], kb2[4];
            #pragma unroll
            for (int i = 0; i < 4; i++) qa[i]  = Qs[(ty * 4 + i) * 64 + k];
            #pragma unroll
            for (int j = 0; j < 4; j++) kb2[j] = Ks[(tx * 4 + j) * 65 + k];
            #pragma unroll
            for (int i = 0; i < 4; i++)
                #pragma unroll
                for (int j = 0; j < 4; j++)
                    s[i][j] = fmaf(qa[i], kb2[j], s[i][j]);
        }

        if (mask) {
            #pragma unroll
            for (int i = 0; i < 4; i++)
                #pragma unroll
                for (int j = 0; j < 4; j++)
                    s[i][j] += mask[(long)(q0 + ty * 4 + i) * 512 + kt * 64 + tx * 4 + j];
        }

        #pragma unroll
        for (int i = 0; i < 4; i++) {
            float tm = fmaxf(fmaxf(s[i][0], s[i][1]), fmaxf(s[i][2], s[i][3]));
            #pragma unroll
            for (int off = 8; off >= 1; off >>= 1)
                tm = fmaxf(tm, __shfl_xor_sync(0xffffffffu, tm, off));
            const float newm = fmaxf(mrow[i], tm);
            float sum = 0.f;
            #pragma unroll
            for (int j = 0; j < 4; j++) {
                const float p = __expf(s[i][j] - newm);
                s[i][j] = p; sum += p;
            }
            #pragma unroll
            for (int off = 8; off >= 1; off >>= 1)
                sum += __shfl_xor_sync(0xffffffffu, sum, off);
            const float corr = __expf(mrow[i] - newm);
            lrow[i] = lrow[i] * corr + sum;
            mrow[i] = newm;
            #pragma unroll
            for (int j = 0; j < 4; j++) o[i][j] *= corr;
            #pragma unroll
            for (int j = 0; j < 4; j++)
                Ps[(ty * 4 + i) * 65 + tx * 4 + j] = s[i][j];
        }
        __syncthreads();

        #pragma unroll 8
        for (int kk = 0; kk < 64; kk++) {
            float pa[4], vb[4];
            #pragma unroll
            for (int i = 0; i < 4; i++) pa[i] = Ps[(ty * 4 + i) * 65 + kk];
            #pragma unroll
            for (int j = 0; j < 4; j++) vb[j] = Vs[kk * 64 + tx * 4 + j];
            #pragma unroll
            for (int i = 0; i < 4; i++)
                #pragma unroll
                for (int j = 0; j < 4; j++)
                    o[i][j] = fmaf(pa[i], vb[j], o[i][j]);
        }
    }

    float* Ob = O + (long)b * 512 * 512;
    #pragma unroll
    for (int i = 0; i < 4; i++) {
        const float inv = 1.f / lrow[i];
        float4 v;
        v.x = o[i][0] * inv; v.y = o[i][1] * inv;
        v.z = o[i][2] * inv; v.w = o[i][3] * inv;
        *(float4*)(Ob + (long)(q0 + ty * 4 + i) * 512 + h * 64 + tx * 4) = v;
    }
}

// ---------------------------------------------------------------------------
// Launch sequence (single stream, graph-capturable, allocation-free)
// ---------------------------------------------------------------------------
extern "C" void kernel_launch(void* const* d_in, const int* in_sizes, int n_in,
                              void* d_out, int out_size)
{
    const float* x             = (const float*)d_in[0];
    const float* mask          = (const float*)d_in[1];
    const float* Wq_inter      = (const float*)d_in[2];
    const float* Wk_inter      = (const float*)d_in[3];
    const float* Wv_inter      = (const float*)d_in[4];
    const float* Wq_intra      = (const float*)d_in[5];
    const float* Wk_intra      = (const float*)d_in[6];
    const float* Wv_intra      = (const float*)d_in[7];
    const float* W_proj_in     = (const float*)d_in[8];
    const float* W_proj_out    = (const float*)d_in[9];
    const float* W_split_inter = (const float*)d_in[10];
    const float* W_out_inter   = (const float*)d_in[11];
    const float* W_split_intra = (const float*)d_in[12];
    const float* W_out_intra   = (const float*)d_in[13];
    const float* alpha         = (const float*)d_in[14];
    float* out = (float*)d_out;

    float *wc_in, *wc_out, *xp, *q, *k, *v, *cc, *oi;
    cudaGetSymbolAddress((void**)&wc_in,  g_Wc_in);
    cudaGetSymbolAddress((void**)&wc_out, g_Wc_out);
    cudaGetSymbolAddress((void**)&xp,     g_xp);
    cudaGetSymbolAddress((void**)&q,      g_q);
    cudaGetSymbolAddress((void**)&k,      g_k);
    cudaGetSymbolAddress((void**)&v,      g_v);
    cudaGetSymbolAddress((void**)&cc,     g_cc);
    cudaGetSymbolAddress((void**)&oi,     g_oi);

    __nv_bfloat16 *xT_hi, *xT_lo, *cc_hi, *cc_lo, *oi_hi, *oi_lo;
    __nv_bfloat16 *wcin_hi, *wcin_lo, *wcout_hi, *wcout_lo;
    __nv_bfloat16 *wsi_hi, *wsi_lo, *woi_hi, *woi_lo;
    cudaGetSymbolAddress((void**)&xT_hi,   g_xT_hi);
    cudaGetSymbolAddress((void**)&xT_lo,   g_xT_lo);
    cudaGetSymbolAddress((void**)&cc_hi,   g_cc_hi);
    cudaGetSymbolAddress((void**)&cc_lo,   g_cc_lo);
    cudaGetSymbolAddress((void**)&oi_hi,   g_oi_hi);
    cudaGetSymbolAddress((void**)&oi_lo,   g_oi_lo);
    cudaGetSymbolAddress((void**)&wcin_hi, g_wcin_hi);
    cudaGetSymbolAddress((void**)&wcin_lo, g_wcin_lo);
    cudaGetSymbolAddress((void**)&wcout_hi,g_wcout_hi);
    cudaGetSymbolAddress((void**)&wcout_lo,g_wcout_lo);
    cudaGetSymbolAddress((void**)&wsi_hi,  g_wsi_hi);
    cudaGetSymbolAddress((void**)&wsi_lo,  g_wsi_lo);
    cudaGetSymbolAddress((void**)&woi_hi,  g_woi_hi);
    cudaGetSymbolAddress((void**)&woi_lo,  g_woi_lo);

    cudaFuncSetAttribute(attn_kernel,
                         cudaFuncAttributeMaxDynamicSharedMemorySize, ATTN_SMEM);
    cudaFuncSetAttribute(tc_gemm<0>,
                         cudaFuncAttributeMaxDynamicSharedMemorySize, TCG_SMEM);
    cudaFuncSetAttribute(tc_gemm<1>,
                         cudaFuncAttributeMaxDynamicSharedMemorySize, TCG_SMEM);
    cudaFuncSetAttribute(tc_gemm<2>,
                         cudaFuncAttributeMaxDynamicSharedMemorySize, TCG_SMEM);

    const long MB = 512L * 512L;
    dim3 tb(256);
    dim3 g1(4, 4, 1);
    dim3 gb(4, 4, BATCH);
    dim3 gq(8, 24, BATCH);
    dim3 ga(8, NH, BATCH);
    dim3 gts(16, 16, BATCH);
    dim3 tts(32, 8);
    const long W4 = (512L * 512) / 4;
    const long X4 = ((long)BATCH * 512 * 512) / 4;

    // Combined weights (fp32):
    // Wc_in[a,s]  = sum_j W_split_inter[a,j] * W_proj_in[j,s]
    gemm512_nt<<<g1, tb>>>(W_split_inter, W_proj_in, wc_in);
    // Wc_out[s,c] = sum_j W_proj_out[s,j] * W_out_inter[j,c]
    gemm512_nt<<<g1, tb>>>(W_proj_out, W_out_inter, wc_out);

    // bf16 hi/lo splits of static operands
    split_kernel<<<(unsigned)((W4 + 255) / 256), 256>>>((const float4*)wc_in,  wcin_hi,  wcin_lo,  W4);
    split_kernel<<<(unsigned)((W4 + 255) / 256), 256>>>((const float4*)wc_out, wcout_hi, wcout_lo, W4);
    split_kernel<<<(unsigned)((W4 + 255) / 256), 256>>>((const float4*)W_split_intra, wsi_hi, wsi_lo, W4);
    split_kernel<<<(unsigned)((W4 + 255) / 256), 256>>>((const float4*)W_out_intra,   woi_hi, woi_lo, W4);
    transpose_split_kernel<<<gts, tts>>>(x, xT_hi, xT_lo);

    // GEMM1: xp[b][r][c] = sum_s xT[b][r][s] * wc_in[c][s]
    tc_gemm<0><<<gb, tb, TCG_SMEM>>>(xT_hi, xT_lo, MB, wcin_hi, wcin_lo, 0,
                                     xp, MB, nullptr, 0, nullptr);

    // inter-path QKV + attention (tokens = feature axis, no mask)
    qkv_kernel<<<gq, tb>>>(xp, Wq_inter, Wk_inter, Wv_inter, q, k, v);
    attn_kernel<<<ga, tb, ATTN_SMEM>>>(q, k, v, nullptr, cc);

    // GEMM2: oi[b][s][d] = sum_k wc_out[s][k] * cc[b][d][k] + x[b][s][d]
    split_kernel<<<(unsigned)((X4 + 255) / 256), 256>>>((const float4*)cc, cc_hi, cc_lo, X4);
    tc_gemm<1><<<gb, tb, TCG_SMEM>>>(wcout_hi, wcout_lo, 0, cc_hi, cc_lo, MB,
                                     oi, MB, x, MB, nullptr);

    // GEMM3: xp = oi @ W_split_intra^T
    split_kernel<<<(unsigned)((X4 + 255) / 256), 256>>>((const float4*)oi, oi_hi, oi_lo, X4);
    tc_gemm<0><<<gb, tb, TCG_SMEM>>>(oi_hi, oi_lo, MB, wsi_hi, wsi_lo, 0,
                                     xp, MB, nullptr, 0, nullptr);

    // intra-path QKV + attention (tokens = sequence, mask added)
    qkv_kernel<<<gq, tb>>>(xp, Wq_intra, Wk_intra, Wv_intra, q, k, v);
    attn_kernel<<<ga, tb, ATTN_SMEM>>>(q, k, v, mask, cc);

    // GEMM4: out = (1-sigmoid(alpha)) * (cc @ W_out_intra^T) + sigmoid(alpha) * oi
    split_kernel<<<(unsigned)((X4 + 255) / 256), 256>>>((const float4*)cc, cc_hi, cc_lo, X4);
    tc_gemm<2><<<gb, tb, TCG_SMEM>>>(cc_hi, cc_lo, MB, woi_hi, woi_lo, 0,
                                     out, MB, oi, MB, alpha);
}

// round 8
// speedup vs baseline: 2.3776x; 1.9439x over previous
#include <cuda_runtime.h>
#include <cuda_bf16.h>
#include <cstdint>

using bf = __nv_bfloat16;
static constexpr int  BATCH = 32;
static constexpr int  NH    = 8;
static constexpr long MB    = 512L * 512L;
static constexpr long HB    = 512L * 64L;

// ---------------------------------------------------------------------------
// Scratch (static __device__ arrays: allocation-free per harness rules)
// ---------------------------------------------------------------------------
__device__ float g_Wc_in [512 * 512];
__device__ float g_Wc_out[512 * 512];
__device__ float g_oi    [(long)BATCH * 512 * 512];

__device__ bf g_xT_hi[(long)BATCH * MB], g_xT_lo[(long)BATCH * MB];
__device__ bf g_xp_hi[(long)BATCH * MB], g_xp_lo[(long)BATCH * MB];
__device__ bf g_cc_hi[(long)BATCH * MB], g_cc_lo[(long)BATCH * MB];
__device__ bf g_oi_hi[(long)BATCH * MB], g_oi_lo[(long)BATCH * MB];
__device__ bf g_q_hi[(long)BATCH * NH * HB], g_q_lo[(long)BATCH * NH * HB];
__device__ bf g_k_hi[(long)BATCH * NH * HB], g_k_lo[(long)BATCH * NH * HB];
__device__ bf g_v_hi[(long)BATCH * NH * HB], g_v_lo[(long)BATCH * NH * HB];

__device__ bf g_wcin_hi [MB], g_wcin_lo [MB];
__device__ bf g_wcout_hi[MB], g_wcout_lo[MB];
__device__ bf g_wsi_hi  [MB], g_wsi_lo  [MB];
__device__ bf g_woi_hi  [MB], g_woi_lo  [MB];
__device__ bf g_wqA_hi[NH*4096], g_wqA_lo[NH*4096];
__device__ bf g_wkA_hi[NH*4096], g_wkA_lo[NH*4096];
__device__ bf g_wvA_hi[NH*4096], g_wvA_lo[NH*4096];
__device__ bf g_wqB_hi[NH*4096], g_wqB_lo[NH*4096];
__device__ bf g_wkB_hi[NH*4096], g_wkB_lo[NH*4096];
__device__ bf g_wvB_hi[NH*4096], g_wvB_lo[NH*4096];

// ---------------------------------------------------------------------------
// Low-level helpers (sm_80+ baseline)
// ---------------------------------------------------------------------------
__device__ __forceinline__ void mma16816(float* c, const uint32_t* a,
                                         uint32_t b0, uint32_t b1) {
    asm volatile(
        "mma.sync.aligned.m16n8k16.row.col.f32.bf16.bf16.f32 "
        "{%0,%1,%2,%3}, {%4,%5,%6,%7}, {%8,%9}, {%0,%1,%2,%3};"
        : "+f"(c[0]), "+f"(c[1]), "+f"(c[2]), "+f"(c[3])
        : "r"(a[0]), "r"(a[1]), "r"(a[2]), "r"(a[3]), "r"(b0), "r"(b1));
}
__device__ __forceinline__ void ldsm4(uint32_t* r, uint32_t a) {
    asm volatile("ldmatrix.sync.aligned.m8n8.x4.shared.b16 {%0,%1,%2,%3}, [%4];"
                 : "=r"(r[0]), "=r"(r[1]), "=r"(r[2]), "=r"(r[3]) : "r"(a));
}
__device__ __forceinline__ void ldsm4t(uint32_t* r, uint32_t a) {
    asm volatile("ldmatrix.sync.aligned.m8n8.x4.trans.shared.b16 {%0,%1,%2,%3}, [%4];"
                 : "=r"(r[0]), "=r"(r[1]), "=r"(r[2]), "=r"(r[3]) : "r"(a));
}
__device__ __forceinline__ void cpa16(uint32_t s, const void* g) {
    asm volatile("cp.async.cg.shared.global [%0], [%1], 16;" :: "r"(s), "l"(g));
}
#define CP_COMMIT() asm volatile("cp.async.commit_group;" ::: "memory")
#define CP_WAIT(N)  asm volatile("cp.async.wait_group %0;" :: "n"(N) : "memory")
__device__ __forceinline__ uint32_t smem_u32(const void* p) {
    uint32_t a;
    asm("{ .reg .u64 t; cvta.to.shared.u64 t, %1; cvt.u32.u64 %0, t; }"
        : "=r"(a) : "l"(p));
    return a;
}
__device__ __forceinline__ void split_pack(float a, float b,
                                           uint32_t& hi, uint32_t& lo) {
    __nv_bfloat162 h, l;
    h.x = __float2bfloat16_rn(a); h.y = __float2bfloat16_rn(b);
    l.x = __float2bfloat16_rn(a - __bfloat162float(h.x));
    l.y = __float2bfloat16_rn(b - __bfloat162float(h.y));
    hi = *reinterpret_cast<uint32_t*>(&h);
    lo = *reinterpret_cast<uint32_t*>(&l);
}
__device__ __forceinline__ void split_store(bf* H, bf* L, long off,
                                            float a, float b) {
    uint32_t h, l; split_pack(a, b, h, l);
    *reinterpret_cast<uint32_t*>(H + off) = h;
    *reinterpret_cast<uint32_t*>(L + off) = l;
}

// ---------------------------------------------------------------------------
// fp32 -> bf16 hi/lo splits (weights only) + x transpose-split
// ---------------------------------------------------------------------------
__global__ __launch_bounds__(256) void split_kernel(
    const float4* __restrict__ in, bf* __restrict__ hi, bf* __restrict__ lo,
    long n4)
{
    long i = (long)blockIdx.x * 256 + threadIdx.x;
    if (i >= n4) return;
    float4 v = in[i];
    uint32_t h0, l0, h1, l1;
    split_pack(v.x, v.y, h0, l0);
    split_pack(v.z, v.w, h1, l1);
    uint2 ph = {h0, h1}, pl = {l0, l1};
    *(uint2*)(hi + i * 4) = ph;
    *(uint2*)(lo + i * 4) = pl;
}

__global__ __launch_bounds__(256) void transpose_split_kernel(
    const float* __restrict__ in, bf* __restrict__ hi, bf* __restrict__ lo)
{
    __shared__ float t[32][33];
    const int b = blockIdx.z;
    const int s0 = blockIdx.x * 32, d0 = blockIdx.y * 32;
    const long base = (long)b * MB;
    const int tx = threadIdx.x, ty = threadIdx.y;
    #pragma unroll
    for (int i = ty; i < 32; i += 8)
        t[i][tx] = in[base + (long)(s0 + i) * 512 + d0 + tx];
    __syncthreads();
    #pragma unroll
    for (int i = ty; i < 32; i += 8) {
        float v = t[tx][i];
        bf h = __float2bfloat16_rn(v);
        bf l = __float2bfloat16_rn(v - __bfloat162float(h));
        long o = base + (long)(d0 + i) * 512 + s0 + tx;
        hi[o] = h; lo[o] = l;
    }
}

// ---------------------------------------------------------------------------
// fp32 weight-combine GEMM: C[m][n] = sum_k A[m,k]*B[k,n], 64x64 tiles
// ---------------------------------------------------------------------------
__global__ __launch_bounds__(256) void gemm64_nt(
    const float* __restrict__ A, const float* __restrict__ B,
    float* __restrict__ C)
{
    __shared__ float As[16][64], Bs[16][64];
    const int bM = blockIdx.y * 64, bN = blockIdx.x * 64;
    const int tid = threadIdx.x, tx = tid & 15, ty = tid >> 4;
    float acc[4][4];
    #pragma unroll
    for (int i = 0; i < 4; i++)
        #pragma unroll
        for (int j = 0; j < 4; j++) acc[i][j] = 0.f;
    for (int kt = 0; kt < 32; kt++) {
        const int k0 = kt * 16;
        __syncthreads();
        #pragma unroll
        for (int it = 0; it < 4; it++) {
            int id = tid + it * 256;
            As[id & 15][id >> 4] = A[(long)(bM + (id >> 4)) * 512 + k0 + (id & 15)];
            Bs[id >> 6][id & 63] = B[(long)(k0 + (id >> 6)) * 512 + bN + (id & 63)];
        }
        __syncthreads();
        #pragma unroll
        for (int k = 0; k < 16; k++) {
            float av[4], bv[4];
            #pragma unroll
            for (int i = 0; i < 4; i++) av[i] = As[k][ty * 4 + i];
            #pragma unroll
            for (int j = 0; j < 4; j++) bv[j] = Bs[k][tx * 4 + j];
            #pragma unroll
            for (int i = 0; i < 4; i++)
                #pragma unroll
                for (int j = 0; j < 4; j++)
                    acc[i][j] = fmaf(av[i], bv[j], acc[i][j]);
        }
    }
    #pragma unroll
    for (int i = 0; i < 4; i++)
        #pragma unroll
        for (int j = 0; j < 4; j++)
            C[(long)(bM + ty * 4 + i) * 512 + bN + tx * 4 + j] = acc[i][j];
}

// ---------------------------------------------------------------------------
// Pipelined tensor-core batched GEMM: C[b][m][n] = sum_k A[b][m][k]*B[b][n][k]
// BK=32, 2-stage cp.async, ldmatrix fragments, 3-term hi/lo accumulation.
// EPI 0: acc  1: acc+R  2: (1-a)*acc + a*R.  OF32 / OBF16 select outputs.
// ---------------------------------------------------------------------------
static constexpr int SK2 = 40;                 // 32+8 pad
static constexpr int ARR = 128 * SK2 * 2;      // bytes per array (10240)
static constexpr int STG = 4 * ARR;            // bytes per stage
static constexpr int TCG_SMEM = 2 * STG;       // 81920

__device__ __forceinline__ void tcg_load(
    uint32_t sb, const bf* Ah, const bf* Al, const bf* Bh, const bf* Bl,
    int bM, int bN, int k0, int tid)
{
    #pragma unroll
    for (int a = 0; a < 4; a++) {
        const bf* src = (a == 0) ? Ah : (a == 1) ? Al : (a == 2) ? Bh : Bl;
        const int row0 = (a < 2) ? bM : bN;
        const uint32_t dst = sb + a * ARR;
        #pragma unroll
        for (int it = 0; it < 2; it++) {
            int id = tid + it * 256;           // 0..511
            int r = id >> 2, c4 = id & 3;
            cpa16(dst + (uint32_t)(r * SK2 + c4 * 8) * 2,
                  src + (long)(row0 + r) * 512 + k0 + c4 * 8);
        }
    }
}

template<int EPI, int OF32, int OBF16>
__global__ __launch_bounds__(256) void tc_gemm(
    const bf* __restrict__ Ahi, const bf* __restrict__ Alo, long sA,
    const bf* __restrict__ Bhi, const bf* __restrict__ Blo, long sB,
    float* __restrict__ C, bf* __restrict__ Chi, bf* __restrict__ Clo, long sC,
    const float* __restrict__ R, long sR, const float* __restrict__ alpha_ptr)
{
    extern __shared__ __align__(16) char smc[];
    const uint32_t sb0 = smem_u32(smc);
    const int tid = threadIdx.x, lane = tid & 31, wid = tid >> 5;
    const int g = lane >> 2, tg = lane & 3;
    const int wm = (wid >> 1) * 32, wn = (wid & 1) * 64;
    const int bN = blockIdx.x * 128, bM = blockIdx.y * 128, bz = blockIdx.z;
    Ahi += (long)bz * sA; Alo += (long)bz * sA;
    Bhi += (long)bz * sB; Blo += (long)bz * sB;
    if (EPI != 0) R += (long)bz * sR;

    float acc[2][8][4];
    #pragma unroll
    for (int i = 0; i < 2; i++)
        #pragma unroll
        for (int j = 0; j < 8; j++)
            #pragma unroll
            for (int q = 0; q < 4; q++) acc[i][j][q] = 0.f;

    tcg_load(sb0, Ahi, Alo, Bhi, Blo, bM, bN, 0, tid);
    CP_COMMIT();

    for (int t = 0; t < 16; t++) {
        if (t < 15) {
            tcg_load(sb0 + ((t + 1) & 1) * STG, Ahi, Alo, Bhi, Blo,
                     bM, bN, (t + 1) * 32, tid);
            CP_COMMIT();
            CP_WAIT(1);
        } else {
            CP_WAIT(0);
        }
        __syncthreads();
        const uint32_t sb = sb0 + (t & 1) * STG;
        #pragma unroll
        for (int ks = 0; ks < 2; ks++) {
            const int kb = ks * 16;
            const uint32_t lrow = (lane & 7) + ((lane >> 3) & 1) * 8;
            const uint32_t lcol = kb + (lane >> 4) * 8;
            uint32_t ah[2][4], al[2][4];
            #pragma unroll
            for (int mi = 0; mi < 2; mi++) {
                uint32_t ad = sb + ((wm + mi * 16 + lrow) * SK2 + lcol) * 2;
                ldsm4(ah[mi], ad);
                ldsm4(al[mi], ad + ARR);
            }
            uint32_t bh[4][4], bl[4][4];
            #pragma unroll
            for (int nb = 0; nb < 4; nb++) {
                uint32_t ad = sb + 2 * ARR + ((wn + nb * 16 + lrow) * SK2 + lcol) * 2;
                ldsm4(bh[nb], ad);
                ldsm4(bl[nb], ad + ARR);
            }
            #pragma unroll
            for (int nb = 0; nb < 4; nb++)
                #pragma unroll
                for (int h2 = 0; h2 < 2; h2++) {
                    const uint32_t b0h = bh[nb][h2], b1h = bh[nb][h2 + 2];
                    const uint32_t b0l = bl[nb][h2], b1l = bl[nb][h2 + 2];
                    #pragma unroll
                    for (int mi = 0; mi < 2; mi++) {
                        float* a = acc[mi][nb * 2 + h2];
                        mma16816(a, ah[mi], b0h, b1h);
                        mma16816(a, ah[mi], b0l, b1l);
                        mma16816(a, al[mi], b0h, b1h);
                    }
                }
        }
        __syncthreads();
    }

    float ab = 0.f;
    if (EPI == 2) ab = 1.f / (1.f + expf(-alpha_ptr[0]));
    #pragma unroll
    for (int mi = 0; mi < 2; mi++)
        #pragma unroll
        for (int nj = 0; nj < 8; nj++) {
            const int row = bM + wm + mi * 16 + g;
            const int col = bN + wn + nj * 8 + tg * 2;
            float v0 = acc[mi][nj][0], v1 = acc[mi][nj][1];
            float v2 = acc[mi][nj][2], v3 = acc[mi][nj][3];
            const long o0 = (long)bz * sC + (long)row * 512 + col;
            const long o1 = o0 + 8 * 512;
            if (EPI == 1) {
                float2 r0 = *(const float2*)(R + (long)row * 512 + col);
                float2 r1 = *(const float2*)(R + (long)(row + 8) * 512 + col);
                v0 += r0.x; v1 += r0.y; v2 += r1.x; v3 += r1.y;
            } else if (EPI == 2) {
                float2 r0 = *(const float2*)(R + (long)row * 512 + col);
                float2 r1 = *(const float2*)(R + (long)(row + 8) * 512 + col);
                v0 = (1.f - ab) * v0 + ab * r0.x;
                v1 = (1.f - ab) * v1 + ab * r0.y;
                v2 = (1.f - ab) * v2 + ab * r1.x;
                v3 = (1.f - ab) * v3 + ab * r1.y;
            }
            if (OF32) {
                float2 w0 = {v0, v1}, w1 = {v2, v3};
                *(float2*)(C + o0) = w0;
                *(float2*)(C + o1) = w1;
            }
            if (OBF16) {
                split_store(Chi, Clo, o0, v0, v1);
                split_store(Chi, Clo, o1, v2, v3);
            }
        }
}

// ---------------------------------------------------------------------------
// QKV projection (mma): per (64-token tile, head, batch).
// X bf16 hi/lo [b][512][512]; W* [h][64(e)][64(d)] hi/lo; out [b*NH+h][512][64]
// ---------------------------------------------------------------------------
static constexpr int SK = 72;
static constexpr int QKV_SMEM = 8 * 64 * SK * 2;   // 73728

__device__ __forceinline__ void head_gemm(
    uint32_t wbase, const uint32_t xh[4][4], const uint32_t xl[4][4],
    float scale, bf* Oh, bf* Ol, long obase, int row0, int lane)
{
    const int g = lane >> 2, tg = lane & 3;
    const uint32_t lrow = (lane & 7) + ((lane >> 3) & 1) * 8;
    const uint32_t lc8 = (lane >> 4) * 8;
    float acc[8][4];
    #pragma unroll
    for (int j = 0; j < 8; j++)
        #pragma unroll
        for (int q = 0; q < 4; q++) acc[j][q] = 0.f;
    #pragma unroll
    for (int ks = 0; ks < 4; ks++) {
        uint32_t bh[4][4], bl[4][4];
        #pragma unroll
        for (int nb = 0; nb < 4; nb++) {
            uint32_t ad = wbase + ((nb * 16 + lrow) * SK + ks * 16 + lc8) * 2;
            ldsm4(bh[nb], ad);
            ldsm4(bl[nb], ad + (uint32_t)(64 * SK * 2));
        }
        #pragma unroll
        for (int nb = 0; nb < 4; nb++)
            #pragma unroll
            for (int h2 = 0; h2 < 2; h2++) {
                float* a = acc[nb * 2 + h2];
                mma16816(a, xh[ks], bh[nb][h2], bh[nb][h2 + 2]);
                mma16816(a, xh[ks], bl[nb][h2], bl[nb][h2 + 2]);
                mma16816(a, xl[ks], bh[nb][h2], bh[nb][h2 + 2]);
            }
    }
    #pragma unroll
    for (int nj = 0; nj < 8; nj++) {
        const long o0 = obase + (long)(row0 + g) * 64 + nj * 8 + tg * 2;
        split_store(Oh, Ol, o0, acc[nj][0] * scale, acc[nj][1] * scale);
        split_store(Oh, Ol, o0 + 8 * 64, acc[nj][2] * scale, acc[nj][3] * scale);
    }
}

__global__ __launch_bounds__(128) void qkv_mma(
    const bf* __restrict__ Xh, const bf* __restrict__ Xl,
    const bf* __restrict__ Wqh, const bf* __restrict__ Wql,
    const bf* __restrict__ Wkh, const bf* __restrict__ Wkl,
    const bf* __restrict__ Wvh, const bf* __restrict__ Wvl,
    bf* __restrict__ Qh, bf* __restrict__ Ql,
    bf* __restrict__ Kh, bf* __restrict__ Kl,
    bf* __restrict__ Vh, bf* __restrict__ Vl)
{
    extern __shared__ __align__(16) bf smq[];
    const int tile0 = blockIdx.x * 64, h = blockIdx.y, b = blockIdx.z;
    const int tid = threadIdx.x, lane = tid & 31, wid = tid >> 5;
    const long xbase = (long)b * MB;
    const long obase = (long)(b * NH + h) * HB;
    bf* Xs = smq;                       // [2][64*SK] hi,lo
    bf* Ws = smq + 2 * 64 * SK;         // 6 arrays: qh,ql,kh,kl,vh,vl

    #pragma unroll
    for (int it = 0; it < 4; it++) {
        int id = tid + it * 128;        // 0..511
        int r = id >> 3, c8 = (id & 7) * 8;
        *(uint4*)(Xs + r * SK + c8) =
            *(const uint4*)(Xh + xbase + (long)(tile0 + r) * 512 + h * 64 + c8);
        *(uint4*)(Xs + 64 * SK + r * SK + c8) =
            *(const uint4*)(Xl + xbase + (long)(tile0 + r) * 512 + h * 64 + c8);
    }
    const bf* wsrc[6] = {Wqh, Wql, Wkh, Wkl, Wvh, Wvl};
    #pragma unroll
    for (int a = 0; a < 6; a++)
        #pragma unroll
        for (int it = 0; it < 4; it++) {
            int id = tid + it * 128;
            int r = id >> 3, c8 = (id & 7) * 8;
            *(uint4*)(Ws + a * 64 * SK + r * SK + c8) =
                *(const uint4*)(wsrc[a] + h * 4096 + r * 64 + c8);
        }
    __syncthreads();

    const uint32_t xb = smem_u32(Xs);
    const uint32_t lrow = (lane & 7) + ((lane >> 3) & 1) * 8;
    const uint32_t lc8 = (lane >> 4) * 8;
    uint32_t xhf[4][4], xlf[4][4];
    #pragma unroll
    for (int ks = 0; ks < 4; ks++) {
        uint32_t ad = xb + ((wid * 16 + lrow) * SK + ks * 16 + lc8) * 2;
        ldsm4(xhf[ks], ad);
        ldsm4(xlf[ks], ad + (uint32_t)(64 * SK * 2));
    }
    const uint32_t wb = smem_u32(Ws);
    const int row0 = tile0 + wid * 16;
    head_gemm(wb,                xhf, xlf, 0.125f, Qh, Ql, obase, row0, lane);
    head_gemm(wb + 2*64*SK*2,    xhf, xlf, 1.f,    Kh, Kl, obase, row0, lane);
    head_gemm(wb + 4*64*SK*2,    xhf, xlf, 1.f,    Vh, Vl, obase, row0, lane);
}

// ---------------------------------------------------------------------------
// Flash attention (mma): per (64-q-row tile, head, batch). Q pre-scaled.
// Output written head-concatenated bf16 hi/lo: O[b][row][h*64+e].
// ---------------------------------------------------------------------------
__global__ __launch_bounds__(128) void attn_mma(
    const bf* __restrict__ Qh, const bf* __restrict__ Ql,
    const bf* __restrict__ Kh, const bf* __restrict__ Kl,
    const bf* __restrict__ Vh, const bf* __restrict__ Vl,
    const float* __restrict__ mask,
    bf* __restrict__ Oh, bf* __restrict__ Ol)
{
    __shared__ __align__(16) bf sma[4 * 64 * SK];   // Kh,Kl,Vh,Vl
    const int q0 = blockIdx.x * 64, h = blockIdx.y, b = blockIdx.z;
    const int tid = threadIdx.x, lane = tid & 31, wid = tid >> 5;
    const int g = lane >> 2, tg = lane & 3;
    const long base = (long)(b * NH + h) * HB;
    const uint32_t sb = smem_u32(sma);
    const uint32_t KH = sb, KL = sb + 64 * SK * 2;
    const uint32_t VH = sb + 2 * 64 * SK * 2, VL = sb + 3 * 64 * SK * 2;
    const uint32_t lrow = (lane & 7) + ((lane >> 3) & 1) * 8;
    const uint32_t lc8 = (lane >> 4) * 8;

    // stage Q tile through K buffers, grab fragments
    #pragma unroll
    for (int it = 0; it < 4; it++) {
        int id = tid + it * 128;
        int r = id >> 3, c8 = (id & 7) * 8;
        *(uint4*)(sma + r * SK + c8) =
            *(const uint4*)(Qh + base + (long)(q0 + r) * 64 + c8);
        *(uint4*)(sma + 64 * SK + r * SK + c8) =
            *(const uint4*)(Ql + base + (long)(q0 + r) * 64 + c8);
    }
    __syncthreads();
    uint32_t qh[4][4], ql[4][4];
    #pragma unroll
    for (int ks = 0; ks < 4; ks++) {
        uint32_t ad = KH + ((wid * 16 + lrow) * SK + ks * 16 + lc8) * 2;
        ldsm4(qh[ks], ad);
        ldsm4(ql[ks], ad + (KL - KH));
    }

    float m0 = -1e30f, m1 = -1e30f, l0 = 0.f, l1 = 0.f;
    float o[8][4];
    #pragma unroll
    for (int j = 0; j < 8; j++)
        #pragma unroll
        for (int q = 0; q < 4; q++) o[j][q] = 0.f;

    for (int kt = 0; kt < 8; kt++) {
        __syncthreads();
        #pragma unroll
        for (int it = 0; it < 4; it++) {
            int id = tid + it * 128;
            int r = id >> 3, c8 = (id & 7) * 8;
            const long gsrc = base + (long)(kt * 64 + r) * 64 + c8;
            *(uint4*)(sma + 0 * 64 * SK + r * SK + c8) = *(const uint4*)(Kh + gsrc);
            *(uint4*)(sma + 1 * 64 * SK + r * SK + c8) = *(const uint4*)(Kl + gsrc);
            *(uint4*)(sma + 2 * 64 * SK + r * SK + c8) = *(const uint4*)(Vh + gsrc);
            *(uint4*)(sma + 3 * 64 * SK + r * SK + c8) = *(const uint4*)(Vl + gsrc);
        }
        __syncthreads();

        // S = Q K^T (3-term)
        float s[8][4];
        #pragma unroll
        for (int j = 0; j < 8; j++)
            #pragma unroll
            for (int q = 0; q < 4; q++) s[j][q] = 0.f;
        #pragma unroll
        for (int ks = 0; ks < 4; ks++) {
            uint32_t bh[4][4], bl[4][4];
            #pragma unroll
            for (int nb = 0; nb < 4; nb++) {
                uint32_t ad = KH + ((nb * 16 + lrow) * SK + ks * 16 + lc8) * 2;
                ldsm4(bh[nb], ad);
                ldsm4(bl[nb], ad + (KL - KH));
            }
            #pragma unroll
            for (int nb = 0; nb < 4; nb++)
                #pragma unroll
                for (int h2 = 0; h2 < 2; h2++) {
                    float* a = s[nb * 2 + h2];
                    mma16816(a, qh[ks], bh[nb][h2], bh[nb][h2 + 2]);
                    mma16816(a, qh[ks], bl[nb][h2], bl[nb][h2 + 2]);
                    mma16816(a, ql[ks], bh[nb][h2], bh[nb][h2 + 2]);
                }
        }
        if (mask) {
            const int mr = q0 + wid * 16 + g;
            #pragma unroll
            for (int nj = 0; nj < 8; nj++) {
                const int mc = kt * 64 + nj * 8 + tg * 2;
                float2 a0 = *(const float2*)(mask + (long)mr * 512 + mc);
                float2 a1 = *(const float2*)(mask + (long)(mr + 8) * 512 + mc);
                s[nj][0] += a0.x; s[nj][1] += a0.y;
                s[nj][2] += a1.x; s[nj][3] += a1.y;
            }
        }

        // online softmax (rows g and g+8; reduce over tg lanes)
        float tm0 = -1e30f, tm1 = -1e30f;
        #pragma unroll
        for (int nj = 0; nj < 8; nj++) {
            tm0 = fmaxf(tm0, fmaxf(s[nj][0], s[nj][1]));
            tm1 = fmaxf(tm1, fmaxf(s[nj][2], s[nj][3]));
        }
        tm0 = fmaxf(tm0, __shfl_xor_sync(~0u, tm0, 1));
        tm0 = fmaxf(tm0, __shfl_xor_sync(~0u, tm0, 2));
        tm1 = fmaxf(tm1, __shfl_xor_sync(~0u, tm1, 1));
        tm1 = fmaxf(tm1, __shfl_xor_sync(~0u, tm1, 2));
        const float nm0 = fmaxf(m0, tm0), nm1 = fmaxf(m1, tm1);
        float sum0 = 0.f, sum1 = 0.f;
        #pragma unroll
        for (int nj = 0; nj < 8; nj++) {
            s[nj][0] = __expf(s[nj][0] - nm0); sum0 += s[nj][0];
            s[nj][1] = __expf(s[nj][1] - nm0); sum0 += s[nj][1];
            s[nj][2] = __expf(s[nj][2] - nm1); sum1 += s[nj][2];
            s[nj][3] = __expf(s[nj][3] - nm1); sum1 += s[nj][3];
        }
        sum0 += __shfl_xor_sync(~0u, sum0, 1);
        sum0 += __shfl_xor_sync(~0u, sum0, 2);
        sum1 += __shfl_xor_sync(~0u, sum1, 1);
        sum1 += __shfl_xor_sync(~0u, sum1, 2);
        const float c0 = __expf(m0 - nm0), c1 = __expf(m1 - nm1);
        l0 = l0 * c0 + sum0; l1 = l1 * c1 + sum1;
        m0 = nm0; m1 = nm1;
        #pragma unroll
        for (int j = 0; j < 8; j++) {
            o[j][0] *= c0; o[j][1] *= c0; o[j][2] *= c1; o[j][3] *= c1;
        }

        // P fragments (FA2 accum->A identity), hi/lo
        uint32_t ph[4][4], pl[4][4];
        #pragma unroll
        for (int ks = 0; ks < 4; ks++) {
            split_pack(s[2*ks][0],   s[2*ks][1],   ph[ks][0], pl[ks][0]);
            split_pack(s[2*ks][2],   s[2*ks][3],   ph[ks][1], pl[ks][1]);
            split_pack(s[2*ks+1][0], s[2*ks+1][1], ph[ks][2], pl[ks][2]);
            split_pack(s[2*ks+1][2], s[2*ks+1][3], ph[ks][3], pl[ks][3]);
        }

        // O += P V  (V^T fragments via ldmatrix.trans)
        #pragma unroll
        for (int ks = 0; ks < 4; ks++) {
            uint32_t vh[4][4], vl[4][4];
            #pragma unroll
            for (int nb = 0; nb < 4; nb++) {
                uint32_t ad = VH + ((ks * 16 + (lane & 15)) * SK + nb * 16 + lc8) * 2;
                ldsm4t(vh[nb], ad);
                ldsm4t(vl[nb], ad + (VL - VH));
            }
            #pragma unroll
            for (int nb = 0; nb < 4; nb++)
                #pragma unroll
                for (int h2 = 0; h2 < 2; h2++) {
                    float* a = o[nb * 2 + h2];
                    const uint32_t b0h = vh[nb][h2 * 2], b1h = vh[nb][h2 * 2 + 1];
                    const uint32_t b0l = vl[nb][h2 * 2], b1l = vl[nb][h2 * 2 + 1];
                    mma16816(a, ph[ks], b0h, b1h);
                    mma16816(a, ph[ks], b0l, b1l);
                    mma16816(a, pl[ks], b0h, b1h);
                }
        }
    }

    const float i0 = 1.f / l0, i1 = 1.f / l1;
    const int row = q0 + wid * 16 + g;
    #pragma unroll
    for (int nj = 0; nj < 8; nj++) {
        const long o0 = (long)b * MB + (long)row * 512 + h * 64 + nj * 8 + tg * 2;
        split_store(Oh, Ol, o0,             o[nj][0] * i0, o[nj][1] * i0);
        split_store(Oh, Ol, o0 + 8 * 512,   o[nj][2] * i1, o[nj][3] * i1);
    }
}

// ---------------------------------------------------------------------------
// Launch sequence (single stream, graph-capturable, allocation-free)
// ---------------------------------------------------------------------------
extern "C" void kernel_launch(void* const* d_in, const int* in_sizes, int n_in,
                              void* d_out, int out_size)
{
    const float* x             = (const float*)d_in[0];
    const float* mask          = (const float*)d_in[1];
    const float* Wq_inter      = (const float*)d_in[2];
    const float* Wk_inter      = (const float*)d_in[3];
    const float* Wv_inter      = (const float*)d_in[4];
    const float* Wq_intra      = (const float*)d_in[5];
    const float* Wk_intra      = (const float*)d_in[6];
    const float* Wv_intra      = (const float*)d_in[7];
    const float* W_proj_in     = (const float*)d_in[8];
    const float* W_proj_out    = (const float*)d_in[9];
    const float* W_split_inter = (const float*)d_in[10];
    const float* W_out_inter   = (const float*)d_in[11];
    const float* W_split_intra = (const float*)d_in[12];
    const float* W_out_intra   = (const float*)d_in[13];
    const float* alpha         = (const float*)d_in[14];
    float* out = (float*)d_out;

    float *wc_in, *wc_out, *oi;
    cudaGetSymbolAddress((void**)&wc_in,  g_Wc_in);
    cudaGetSymbolAddress((void**)&wc_out, g_Wc_out);
    cudaGetSymbolAddress((void**)&oi,     g_oi);

    bf *xTh,*xTl,*xph,*xpl,*cch,*ccl,*oih,*oil,*qhh,*qll,*khh,*kll,*vhh,*vll;
    bf *wcinh,*wcinl,*wcouth,*wcoutl,*wsih,*wsil,*woih,*woil;
    bf *wqAh,*wqAl,*wkAh,*wkAl,*wvAh,*wvAl,*wqBh,*wqBl,*wkBh,*wkBl,*wvBh,*wvBl;
    cudaGetSymbolAddress((void**)&xTh, g_xT_hi); cudaGetSymbolAddress((void**)&xTl, g_xT_lo);
    cudaGetSymbolAddress((void**)&xph, g_xp_hi); cudaGetSymbolAddress((void**)&xpl, g_xp_lo);
    cudaGetSymbolAddress((void**)&cch, g_cc_hi); cudaGetSymbolAddress((void**)&ccl, g_cc_lo);
    cudaGetSymbolAddress((void**)&oih, g_oi_hi); cudaGetSymbolAddress((void**)&oil, g_oi_lo);
    cudaGetSymbolAddress((void**)&qhh, g_q_hi);  cudaGetSymbolAddress((void**)&qll, g_q_lo);
    cudaGetSymbolAddress((void**)&khh, g_k_hi);  cudaGetSymbolAddress((void**)&kll, g_k_lo);
    cudaGetSymbolAddress((void**)&vhh, g_v_hi);  cudaGetSymbolAddress((void**)&vll, g_v_lo);
    cudaGetSymbolAddress((void**)&wcinh, g_wcin_hi);  cudaGetSymbolAddress((void**)&wcinl, g_wcin_lo);
    cudaGetSymbolAddress((void**)&wcouth, g_wcout_hi);cudaGetSymbolAddress((void**)&wcoutl, g_wcout_lo);
    cudaGetSymbolAddress((void**)&wsih, g_wsi_hi);    cudaGetSymbolAddress((void**)&wsil, g_wsi_lo);
    cudaGetSymbolAddress((void**)&woih, g_woi_hi);    cudaGetSymbolAddress((void**)&woil, g_woi_lo);
    cudaGetSymbolAddress((void**)&wqAh, g_wqA_hi); cudaGetSymbolAddress((void**)&wqAl, g_wqA_lo);
    cudaGetSymbolAddress((void**)&wkAh, g_wkA_hi); cudaGetSymbolAddress((void**)&wkAl, g_wkA_lo);
    cudaGetSymbolAddress((void**)&wvAh, g_wvA_hi); cudaGetSymbolAddress((void**)&wvAl, g_wvA_lo);
    cudaGetSymbolAddress((void**)&wqBh, g_wqB_hi); cudaGetSymbolAddress((void**)&wqBl, g_wqB_lo);
    cudaGetSymbolAddress((void**)&wkBh, g_wkB_hi); cudaGetSymbolAddress((void**)&wkBl, g_wkB_lo);
    cudaGetSymbolAddress((void**)&wvBh, g_wvB_hi); cudaGetSymbolAddress((void**)&wvBl, g_wvB_lo);

    cudaFuncSetAttribute(tc_gemm<0,0,1>, cudaFuncAttributeMaxDynamicSharedMemorySize, TCG_SMEM);
    cudaFuncSetAttribute(tc_gemm<1,1,1>, cudaFuncAttributeMaxDynamicSharedMemorySize, TCG_SMEM);
    cudaFuncSetAttribute(tc_gemm<2,1,0>, cudaFuncAttributeMaxDynamicSharedMemorySize, TCG_SMEM);
    cudaFuncSetAttribute(qkv_mma, cudaFuncAttributeMaxDynamicSharedMemorySize, QKV_SMEM);

    dim3 gw(8, 8, 1);
    dim3 gb(4, 4, BATCH);
    dim3 gq(8, NH, BATCH);
    dim3 gts(16, 16, BATCH), tts(32, 8);
    const long W4 = MB / 4, H4 = (long)NH * 4096 / 4;

    // combined weights (fp32) + splits
    gemm64_nt<<<gw, 256>>>(W_split_inter, W_proj_in, wc_in);
    gemm64_nt<<<gw, 256>>>(W_proj_out, W_out_inter, wc_out);
    split_kernel<<<256, 256>>>((const float4*)wc_in,  wcinh,  wcinl,  W4);
    split_kernel<<<256, 256>>>((const float4*)wc_out, wcouth, wcoutl, W4);
    split_kernel<<<256, 256>>>((const float4*)W_split_intra, wsih, wsil, W4);
    split_kernel<<<256, 256>>>((const float4*)W_out_intra,   woih, woil, W4);
    split_kernel<<<32, 256>>>((const float4*)Wq_inter, wqAh, wqAl, H4);
    split_kernel<<<32, 256>>>((const float4*)Wk_inter, wkAh, wkAl, H4);
    split_kernel<<<32, 256>>>((const float4*)Wv_inter, wvAh, wvAl, H4);
    split_kernel<<<32, 256>>>((const float4*)Wq_intra, wqBh, wqBl, H4);
    split_kernel<<<32, 256>>>((const float4*)Wk_intra, wkBh, wkBl, H4);
    split_kernel<<<32, 256>>>((const float4*)Wv_intra, wvBh, wvBl, H4);
    transpose_split_kernel<<<gts, tts>>>(x, xTh, xTl);

    // GEMM1: xp = xT @ wcin^T  (bf16 out)
    tc_gemm<0,0,1><<<gb, 256, TCG_SMEM>>>(xTh, xTl, MB, wcinh, wcinl, 0,
                                          nullptr, xph, xpl, MB, nullptr, 0, nullptr);
    // inter path
    qkv_mma<<<gq, 128, QKV_SMEM>>>(xph, xpl, wqAh, wqAl, wkAh, wkAl, wvAh, wvAl,
                                   qhh, qll, khh, kll, vhh, vll);
    attn_mma<<<gq, 128>>>(qhh, qll, khh, kll, vhh, vll, nullptr, cch, ccl);
    // GEMM2: oi = wcout @ cc^T + x  (fp32 + bf16 out)
    tc_gemm<1,1,1><<<gb, 256, TCG_SMEM>>>(wcouth, wcoutl, 0, cch, ccl, MB,
                                          oi, oih, oil, MB, x, MB, nullptr);
    // GEMM3: xi = oi @ wsi^T  (bf16 out, reuse xp)
    tc_gemm<0,0,1><<<gb, 256, TCG_SMEM>>>(oih, oil, MB, wsih, wsil, 0,
                                          nullptr, xph, xpl, MB, nullptr, 0, nullptr);
    // intra path
    qkv_mma<<<gq, 128, QKV_SMEM>>>(xph, xpl, wqBh, wqBl, wkBh, wkBl, wvBh, wvBl,
                                   qhh, qll, khh, kll, vhh, vll);
    attn_mma<<<gq, 128>>>(qhh, qll, khh, kll, vhh, vll, mask, cch, ccl);
    // GEMM4: out = (1-a)*(cc @ woi^T) + a*oi
    tc_gemm<2,1,0><<<gb, 256, TCG_SMEM>>>(cch, ccl, MB, woih, woil, 0,
                                          out, nullptr, nullptr, MB, oi, MB, alpha);
}